// round 1
// baseline (speedup 1.0000x reference)
#include <cuda_runtime.h>
#include <cuda_bf16.h>
#include <math.h>

// ---------------- constants ----------------
#define B_   2
#define L_   2048
#define DM   1024          // D_MODEL
#define NH   16            // NHEAD
#define HD   64            // HD_ATT
#define DI   2048          // D_INNER
#define HS   32            // H_SSM
#define P_   64            // HEADDIM
#define NST  128           // D_STATE
#define CONVD 2304         // CONV_DIM
#define DINP 4384          // D_IN_PROJ
#define CH   256           // CHUNK
#define NC   8             // L/CHUNK
#define DFF  2048
#define ALPHA 1.68f
#define EPSN 1e-5f

#define ROWS (B_*L_)       // 4096

// ---------------- scratch ----------------
// offsets (floats)
__device__ __constant__ int dummy_c; // keep nvcc happy

static const long long SZ_BIG  = (long long)ROWS*DINP;    // 17,956,864
static const long long SZ_HB   = (long long)ROWS*DM;
static const long long SZ_XBC  = (long long)ROWS*CONVD;
static const long long SZ_DT   = (long long)ROWS*HS;
static const long long SZ_XDT  = (long long)ROWS*DI;
static const long long SZ_ACS  = (long long)B_*HS*L_;
static const long long SZ_CB   = (long long)B_*NC*CH*CH;
static const long long SZ_ST   = (long long)B_*HS*NC*NST*P_;
static const long long SZ_Y    = (long long)ROWS*DI;

static const long long OFF_BIG = 0;
static const long long OFF_H   = OFF_BIG + SZ_BIG;
static const long long OFF_O   = OFF_H   + SZ_HB;
static const long long OFF_X   = OFF_O   + SZ_HB;
static const long long OFF_XBC = OFF_X   + SZ_HB;
static const long long OFF_DT  = OFF_XBC + SZ_XBC;
static const long long OFF_XDT = OFF_DT  + SZ_DT;
static const long long OFF_ACS = OFF_XDT + SZ_XDT;
static const long long OFF_CB  = OFF_ACS + SZ_ACS;
static const long long OFF_STA = OFF_CB  + SZ_CB;
static const long long OFF_SPR = OFF_STA + SZ_ST;
static const long long OFF_Y   = OFF_SPR + SZ_ST;
static const long long OFF_FF  = OFF_Y   + SZ_Y;
static const long long TOTALF  = OFF_FF  + SZ_Y;

__device__ float g_scratch[74842112]; // == TOTALF floats (~300 MB)

// ---------------- helpers ----------------
__device__ __forceinline__ float silu_f(float x) {
    return x / (1.f + __expf(-x));
}
__device__ __forceinline__ float softplus_f(float x) {
    return (x > 20.f) ? x : log1pf(__expf(x));
}

// ---------------- generic NT GEMM: C[M,N] = A[M,K] @ W[N,K]^T (+bias) ----------------
__global__ void gemm_nt(const float* __restrict__ A, const float* __restrict__ W,
                        const float* __restrict__ bias, float* __restrict__ C,
                        int M, int N, int K, int lda, int ldw, int ldc,
                        long long sA, long long sW, long long sC)
{
    A += (long long)blockIdx.z * sA;
    W += (long long)blockIdx.z * sW;
    C += (long long)blockIdx.z * sC;
    __shared__ float As[16][65];
    __shared__ float Ws[16][65];
    int bm = blockIdx.y * 64, bn = blockIdx.x * 64;
    int tx = threadIdx.x, ty = threadIdx.y;
    int tid = ty * 16 + tx;
    float acc[4][4] = {};
    for (int k0 = 0; k0 < K; k0 += 16) {
        #pragma unroll
        for (int i = 0; i < 4; i++) {
            int idx = tid + i * 256;
            int m = idx >> 4, k = idx & 15;
            int gm = bm + m;
            As[k][m] = (gm < M) ? A[(long long)gm * lda + k0 + k] : 0.f;
            int gn = bn + m;
            Ws[k][m] = (gn < N) ? W[(long long)gn * ldw + k0 + k] : 0.f;
        }
        __syncthreads();
        #pragma unroll
        for (int k = 0; k < 16; k++) {
            float ar[4], wr[4];
            #pragma unroll
            for (int i = 0; i < 4; i++) ar[i] = As[k][ty * 4 + i];
            #pragma unroll
            for (int j = 0; j < 4; j++) wr[j] = Ws[k][tx * 4 + j];
            #pragma unroll
            for (int i = 0; i < 4; i++)
                #pragma unroll
                for (int j = 0; j < 4; j++) acc[i][j] += ar[i] * wr[j];
        }
        __syncthreads();
    }
    #pragma unroll
    for (int i = 0; i < 4; i++) {
        int gm = bm + ty * 4 + i;
        if (gm >= M) continue;
        #pragma unroll
        for (int j = 0; j < 4; j++) {
            int gn = bn + tx * 4 + j;
            if (gn < N)
                C[(long long)gm * ldc + gn] = acc[i][j] + (bias ? bias[gn] : 0.f);
        }
    }
}

// ---------------- rmsnorm: out = rmsnorm(a + alpha*b, w), row-parallel ----------------
__global__ void rmsnorm_kernel(const float* __restrict__ a, const float* __restrict__ b,
                               float alpha, const float* __restrict__ w,
                               float* __restrict__ out, int D)
{
    long long row = blockIdx.x;
    const float* ap = a + row * D;
    const float* bp = b ? (b + row * D) : nullptr;
    int per = D >> 8;           // D/256, D in {1024,2048}
    float v[8];
    float ss = 0.f;
    for (int j = 0; j < per; j++) {
        int i = threadIdx.x + j * 256;
        float x = ap[i] + (bp ? alpha * bp[i] : 0.f);
        v[j] = x;
        ss += x * x;
    }
    __shared__ float red[256];
    red[threadIdx.x] = ss;
    __syncthreads();
    for (int off = 128; off; off >>= 1) {
        if (threadIdx.x < off) red[threadIdx.x] += red[threadIdx.x + off];
        __syncthreads();
    }
    float scale = rsqrtf(red[0] / D + EPSN);
    float* op = out + row * D;
    for (int j = 0; j < per; j++) {
        int i = threadIdx.x + j * 256;
        op[i] = v[j] * scale * w[i];
    }
}

// ---------------- gated rmsnorm: out = rmsnorm(y * silu(z), w), D=2048 ----------------
__global__ void gated_rmsnorm_kernel(const float* __restrict__ y, const float* __restrict__ z,
                                     int ldz, const float* __restrict__ w,
                                     float* __restrict__ out)
{
    long long row = blockIdx.x;
    const float* yp = y + row * DI;
    const float* zp = z + row * (long long)ldz;
    float v[8];
    float ss = 0.f;
    #pragma unroll
    for (int j = 0; j < 8; j++) {
        int i = threadIdx.x + j * 256;
        float x = yp[i] * silu_f(zp[i]);
        v[j] = x;
        ss += x * x;
    }
    __shared__ float red[256];
    red[threadIdx.x] = ss;
    __syncthreads();
    for (int off = 128; off; off >>= 1) {
        if (threadIdx.x < off) red[threadIdx.x] += red[threadIdx.x + off];
        __syncthreads();
    }
    float scale = rsqrtf(red[0] / DI + EPSN);
    float* op = out + row * DI;
    #pragma unroll
    for (int j = 0; j < 8; j++) {
        int i = threadIdx.x + j * 256;
        op[i] = v[j] * scale * w[i];
    }
}

// ---------------- flash attention (non-causal) ----------------
// qkv layout per row: [q(16x64) | k(16x64) | v(16x64)]   (3072)
// grid: (L/64, B*NH), 64 threads; each thread one query row.
__global__ void attn_kernel(const float* __restrict__ qkv, float* __restrict__ o)
{
    __shared__ float Ksh[64][64];
    __shared__ float Vsh[64][64];
    int bh = blockIdx.y;
    int b = bh >> 4, h = bh & 15;
    int l = blockIdx.x * 64 + threadIdx.x;
    const float* qp = qkv + ((long long)(b * L_ + l) * 3072) + h * 64;
    float q[64], acc[64];
    #pragma unroll
    for (int d = 0; d < 64; d++) { q[d] = qp[d] * 0.125f; acc[d] = 0.f; }
    float m = -1e30f, lsum = 0.f;
    for (int kt = 0; kt < L_ / 64; kt++) {
        const float* kb = qkv + ((long long)(b * L_ + kt * 64) * 3072) + 1024 + h * 64;
        const float* vb = kb + 1024;
        for (int r = 0; r < 64; r++) {
            Ksh[r][threadIdx.x] = kb[(long long)r * 3072 + threadIdx.x];
            Vsh[r][threadIdx.x] = vb[(long long)r * 3072 + threadIdx.x];
        }
        __syncthreads();
        for (int j = 0; j < 64; j++) {
            float s = 0.f;
            #pragma unroll
            for (int d = 0; d < 64; d++) s += q[d] * Ksh[j][d];
            float p;
            if (s > m) {
                float corr = __expf(m - s);
                #pragma unroll
                for (int d = 0; d < 64; d++) acc[d] *= corr;
                lsum *= corr;
                m = s;
                p = 1.f;
            } else {
                p = __expf(s - m);
            }
            lsum += p;
            #pragma unroll
            for (int d = 0; d < 64; d++) acc[d] += p * Vsh[j][d];
        }
        __syncthreads();
    }
    float inv = 1.f / lsum;
    float* op = o + ((long long)(b * L_ + l) * DM) + h * 64;
    #pragma unroll
    for (int d = 0; d < 64; d++) op[d] = acc[d] * inv;
}

// ---------------- depthwise causal conv (k=4) + bias + silu ----------------
// in: zxbcdt[..., DI : DI+CONVD], out: xBC (ROWS x CONVD)
__global__ void conv_kernel(const float* __restrict__ zx, const float* __restrict__ cw,
                            const float* __restrict__ cb, float* __restrict__ xbc)
{
    int idx = blockIdx.x * 256 + threadIdx.x;
    if (idx >= B_ * L_ * CONVD) return;
    int c = idx % CONVD;
    int t = (idx / CONVD) % L_;
    int b = idx / (CONVD * L_);
    float s = cb[c];
    #pragma unroll
    for (int k = 0; k < 4; k++) {
        int tt = t - 3 + k;
        if (tt >= 0)
            s += zx[((long long)(b * L_ + tt) * DINP) + DI + c] * cw[c * 4 + k];
    }
    xbc[idx] = silu_f(s);
}

// ---------------- dt (softplus) and xdt = xs*dt ----------------
__global__ void dtxdt_kernel(const float* __restrict__ zx, const float* __restrict__ xbc,
                             const float* __restrict__ dt_bias,
                             float* __restrict__ dtb, float* __restrict__ xdt)
{
    int idx = blockIdx.x * 256 + threadIdx.x;   // over ROWS*DI
    if (idx >= ROWS * DI) return;
    int p = idx & 63;
    int h = (idx >> 6) & 31;
    long long row = idx >> 11;
    float raw = zx[row * DINP + DI + CONVD + h] + dt_bias[h];
    float d = softplus_f(raw);
    xdt[idx] = xbc[row * CONVD + h * 64 + p] * d;
    if (p == 0) dtb[row * HS + h] = d;
}

// ---------------- per-chunk inclusive cumsum of a = -exp(A_log[h])*dt ----------------
// grid: B*HS*NC, 256 threads. Acs layout: [b*HS+h][L]
__global__ void cumsum_kernel(const float* __restrict__ dtb, const float* __restrict__ A_log,
                              float* __restrict__ Acs)
{
    __shared__ float s[256];
    int blk = blockIdx.x;
    int ck = blk & 7;
    int bh = blk >> 3;
    int h = bh & 31;
    int b = bh >> 5;
    int l = threadIdx.x;
    int gl = ck * 256 + l;
    float a = -__expf(A_log[h]) * dtb[((long long)(b * L_ + gl)) * HS + h];
    s[l] = a;
    __syncthreads();
    for (int off = 1; off < 256; off <<= 1) {
        float t = (l >= off) ? s[l - off] : 0.f;
        __syncthreads();
        s[l] += t;
        __syncthreads();
    }
    Acs[(long long)bh * L_ + gl] = s[l];
}

// ---------------- chunk states: st[n,p] = sum_l B[l,n]*exp(AcsLast-Acs[l])*xdt[l,p] ----------------
// grid: B*HS*NC, 128 threads (thread = n). states layout [(bh*NC+ck)][n][p]
__global__ void states_kernel(const float* __restrict__ xbc, const float* __restrict__ xdt,
                              const float* __restrict__ Acs, float* __restrict__ states)
{
    __shared__ float xs_sh[8][64];
    __shared__ float dec[256];
    int blk = blockIdx.x;
    int ck = blk & 7;
    int bh = blk >> 3;
    int h = bh & 31;
    int b = bh >> 5;
    int n = threadIdx.x;
    const float* acs = Acs + (long long)bh * L_ + ck * 256;
    float aLast = acs[255];
    for (int i = n; i < 256; i += 128) dec[i] = __expf(aLast - acs[i]);
    float acc[64];
    #pragma unroll
    for (int p = 0; p < 64; p++) acc[p] = 0.f;
    long long rowbase = (long long)(b * L_ + ck * 256);
    for (int lt = 0; lt < 32; lt++) {
        __syncthreads();
        #pragma unroll
        for (int i = 0; i < 4; i++) {
            int idx = n + i * 128;
            int r = idx >> 6, p = idx & 63;
            xs_sh[r][p] = xdt[(rowbase + lt * 8 + r) * DI + h * 64 + p];
        }
        __syncthreads();
        #pragma unroll
        for (int r = 0; r < 8; r++) {
            int l = lt * 8 + r;
            float w = xbc[(rowbase + l) * CONVD + DI + n] * dec[l];
            #pragma unroll
            for (int p = 0; p < 64; p++) acc[p] += w * xs_sh[r][p];
        }
    }
    float* op = states + ((long long)(bh * NC + ck) * NST + n) * P_;
    #pragma unroll
    for (int p = 0; p < 64; p++) op[p] = acc[p];
}

// ---------------- inter-chunk scan: Sprev[c]=S; S = S*exp(Asum_c) + states[c] ----------------
// grid: B*HS, 256 threads; 8192 elems per (b,h), 32 per thread.
__global__ void scan_kernel(const float* __restrict__ states, const float* __restrict__ Acs,
                            float* __restrict__ Sprev)
{
    int bh = blockIdx.x;
    int tid = threadIdx.x;
    float S[32];
    #pragma unroll
    for (int j = 0; j < 32; j++) S[j] = 0.f;
    for (int c = 0; c < NC; c++) {
        float dc = __expf(Acs[(long long)bh * L_ + c * 256 + 255]);
        const float* sp = states + (long long)(bh * NC + c) * 8192;
        float* pp = Sprev + (long long)(bh * NC + c) * 8192;
        #pragma unroll
        for (int j = 0; j < 32; j++) {
            int idx = tid + j * 256;
            pp[idx] = S[j];
            S[j] = S[j] * dc + sp[idx];
        }
    }
}

// ---------------- Y: diag + off-diag + D*xs ----------------
// grid: B*HS*NC, 256 threads (thread = l within chunk)
__global__ void y_kernel(const float* __restrict__ xbc, const float* __restrict__ xdt,
                         const float* __restrict__ Acs, const float* __restrict__ CB,
                         const float* __restrict__ Sprev, const float* __restrict__ Dv,
                         float* __restrict__ Y)
{
    __shared__ float sh[128 * 64];   // 32KB: Sprev, then x-tiles
    __shared__ float acs_sh[256];
    int blk = blockIdx.x;
    int ck = blk & 7;
    int bh = blk >> 3;
    int h = bh & 31;
    int b = bh >> 5;
    int l = threadIdx.x;
    int gl = ck * 256 + l;
    long long row = (long long)(b * L_ + gl);

    acs_sh[l] = Acs[(long long)bh * L_ + gl];
    // stage Sprev [n][p]
    const float* spv = Sprev + (long long)(bh * NC + ck) * 8192;
    #pragma unroll
    for (int j = 0; j < 32; j++) sh[l + j * 256] = spv[l + j * 256];
    __syncthreads();

    float aL = acs_sh[l];
    float y[64];
    #pragma unroll
    for (int p = 0; p < 64; p++) y[p] = 0.f;

    // off-diagonal: y += exp(aL) * sum_n C[l,n]*Sprev[n,:]
    {
        float eA = __expf(aL);
        const float* cp = xbc + row * CONVD + DI + NST;
        for (int n = 0; n < 128; n++) {
            float cn = cp[n] * eA;
            const float* sr = &sh[n * 64];
            #pragma unroll
            for (int p = 0; p < 64; p++) y[p] += cn * sr[p];
        }
    }

    // diagonal: y += sum_{s<=l} CB[s,l]*exp(aL-acs[s]) * xdt[s,:]
    const float* cbp = CB + (long long)(b * NC + ck) * (CH * CH);
    long long rowbase = (long long)(b * L_ + ck * 256);
    for (int st = 0; st < 4; st++) {
        __syncthreads();
        #pragma unroll
        for (int j = 0; j < 16; j++) {
            int idx = l + j * 256;
            int r = idx >> 6, p = idx & 63;
            sh[r * 64 + p] = xdt[(rowbase + st * 64 + r) * DI + h * 64 + p];
        }
        __syncthreads();
        for (int r = 0; r < 64; r++) {
            int s = st * 64 + r;
            if (s <= l) {
                float w = cbp[s * 256 + l] * __expf(aL - acs_sh[s]);
                const float* xr = &sh[r * 64];
                #pragma unroll
                for (int p = 0; p < 64; p++) y[p] += w * xr[p];
            }
        }
    }

    float Dh = Dv[h];
    const float* xsrow = xbc + row * CONVD + h * 64;
    float* op = Y + row * DI + h * 64;
    #pragma unroll
    for (int p = 0; p < 64; p++) op[p] = y[p] + Dh * xsrow[p];
}

// ---------------- swiglu: ff[f] = y1[f] * silu(y[f+2048]) ----------------
__global__ void swiglu_kernel(const float* __restrict__ y, float* __restrict__ ff)
{
    int idx = blockIdx.x * 256 + threadIdx.x;
    if (idx >= ROWS * DFF) return;
    long long row = idx / DFF;
    int f = idx % DFF;
    const float* yp = y + row * (2 * DFF);
    ff[idx] = yp[f] * silu_f(yp[f + DFF]);
}

// ---------------- host launcher ----------------
extern "C" void kernel_launch(void* const* d_in, const int* in_sizes, int n_in,
                              void* d_out, int out_size)
{
    const float* x_in       = (const float*)d_in[0];
    const float* attn_norm  = (const float*)d_in[1];
    const float* Wqkv       = (const float*)d_in[2];
    const float* Wqkv_b     = (const float*)d_in[3];
    const float* attn_out_w = (const float*)d_in[4];
    const float* attn_out_b = (const float*)d_in[5];
    const float* normf_w    = (const float*)d_in[6];
    const float* m_in_w     = (const float*)d_in[7];
    const float* m_conv_w   = (const float*)d_in[8];
    const float* m_conv_b   = (const float*)d_in[9];
    const float* m_dt_bias  = (const float*)d_in[10];
    const float* m_A_log    = (const float*)d_in[11];
    const float* m_D        = (const float*)d_in[12];
    const float* m_norm_w   = (const float*)d_in[13];
    const float* m_out_w    = (const float*)d_in[14];
    const float* fc1_w      = (const float*)d_in[15];
    const float* fc2_w      = (const float*)d_in[16];
    const float* final_norm = (const float*)d_in[17];
    float* out = (float*)d_out;

    float* scr = nullptr;
    cudaGetSymbolAddress((void**)&scr, g_scratch);

    float* bBIG = scr + OFF_BIG;
    float* bH   = scr + OFF_H;
    float* bO   = scr + OFF_O;
    float* bX   = scr + OFF_X;
    float* bXBC = scr + OFF_XBC;
    float* bDT  = scr + OFF_DT;
    float* bXDT = scr + OFF_XDT;
    float* bACS = scr + OFF_ACS;
    float* bCB  = scr + OFF_CB;
    float* bSTA = scr + OFF_STA;
    float* bSPR = scr + OFF_SPR;
    float* bY   = scr + OFF_Y;
    float* bFF  = scr + OFF_FF;

    dim3 gthr(16, 16);

    // ---- attention block ----
    rmsnorm_kernel<<<ROWS, 256>>>(x_in, nullptr, 0.f, attn_norm, bH, DM);
    gemm_nt<<<dim3(3072/64, ROWS/64, 1), gthr>>>(bH, Wqkv, Wqkv_b, bBIG,
        ROWS, 3072, DM, DM, DM, 3072, 0, 0, 0);
    attn_kernel<<<dim3(L_/64, B_*NH), 64>>>(bBIG, bO);
    gemm_nt<<<dim3(DM/64, ROWS/64, 1), gthr>>>(bO, attn_out_w, attn_out_b, bH,
        ROWS, DM, DM, DM, DM, DM, 0, 0, 0);
    rmsnorm_kernel<<<ROWS, 256>>>(bH, x_in, 1.f, normf_w, bX, DM);

    // ---- mamba layers ----
    for (int i = 0; i < 4; i++) {
        const float* in_w   = m_in_w   + (long long)i * DINP * DM;
        const float* conv_w = m_conv_w + (long long)i * CONVD * 4;
        const float* conv_b = m_conv_b + (long long)i * CONVD;
        const float* dtbias = m_dt_bias+ (long long)i * HS;
        const float* Alog   = m_A_log  + (long long)i * HS;
        const float* Dv     = m_D      + (long long)i * HS;
        const float* nw     = m_norm_w + (long long)i * DI;
        const float* ow     = m_out_w  + (long long)i * DM * DI;

        gemm_nt<<<dim3((DINP+63)/64, ROWS/64, 1), gthr>>>(bX, in_w, nullptr, bBIG,
            ROWS, DINP, DM, DM, DM, DINP, 0, 0, 0);
        conv_kernel<<<(ROWS*CONVD)/256, 256>>>(bBIG, conv_w, conv_b, bXBC);
        dtxdt_kernel<<<(ROWS*DI)/256, 256>>>(bBIG, bXBC, dtbias, bDT, bXDT);
        cumsum_kernel<<<B_*HS*NC, 256>>>(bDT, Alog, bACS);
        // CB[b,c][s][l] = Bm[s] . Cm[l]  (batched over b*c = 16)
        gemm_nt<<<dim3(4, 4, B_*NC), gthr>>>(
            bXBC + DI, bXBC + DI + NST, nullptr, bCB,
            CH, CH, NST, CONVD, CONVD, CH,
            (long long)CH * CONVD, (long long)CH * CONVD, (long long)CH * CH);
        states_kernel<<<B_*HS*NC, 128>>>(bXBC, bXDT, bACS, bSTA);
        scan_kernel<<<B_*HS, 256>>>(bSTA, bACS, bSPR);
        y_kernel<<<B_*HS*NC, 256>>>(bXBC, bXDT, bACS, bCB, bSPR, Dv, bY);
        gated_rmsnorm_kernel<<<ROWS, 256>>>(bY, bBIG, DINP, nw, bY);
        gemm_nt<<<dim3(DM/64, ROWS/64, 1), gthr>>>(bY, ow, nullptr, bX,
            ROWS, DM, DI, DI, DI, DM, 0, 0, 0);
    }

    // ---- MLP + final norm ----
    gemm_nt<<<dim3(4096/64, ROWS/64, 1), gthr>>>(bX, fc1_w, nullptr, bBIG,
        ROWS, 2*DFF, DM, DM, DM, 2*DFF, 0, 0, 0);
    swiglu_kernel<<<(ROWS*DFF)/256, 256>>>(bBIG, bFF);
    gemm_nt<<<dim3(DM/64, ROWS/64, 1), gthr>>>(bFF, fc2_w, nullptr, bH,
        ROWS, DM, DFF, DFF, DFF, DM, 0, 0, 0);
    rmsnorm_kernel<<<ROWS, 256>>>(bH, bX, ALPHA, final_norm, out, DM);
}

// round 3
// speedup vs baseline: 1.8953x; 1.8953x over previous
#include <cuda_runtime.h>
#include <cuda_bf16.h>
#include <math.h>
#include <stdint.h>

// ---------------- constants ----------------
#define B_   2
#define L_   2048
#define DM   1024          // D_MODEL
#define NH   16            // NHEAD
#define HD   64            // HD_ATT
#define DI   2048          // D_INNER
#define HS   32            // H_SSM
#define P_   64            // HEADDIM
#define NST  128           // D_STATE
#define CONVD 2304         // CONV_DIM
#define DINP 4384          // D_IN_PROJ
#define CH   256           // CHUNK
#define NC   8             // L/CHUNK
#define DFF  2048
#define ALPHA 1.68f
#define EPSN 1e-5f

#define ROWS (B_*L_)       // 4096

// ---------------- scratch ----------------
static const long long SZ_BIG  = (long long)ROWS*DINP;
static const long long SZ_HB   = (long long)ROWS*DM;
static const long long SZ_XBC  = (long long)ROWS*CONVD;
static const long long SZ_DT   = (long long)ROWS*HS;
static const long long SZ_XDT  = (long long)ROWS*DI;
static const long long SZ_ACS  = (long long)B_*HS*L_;
static const long long SZ_CB   = (long long)B_*NC*CH*CH;
static const long long SZ_ST   = (long long)B_*HS*NC*NST*P_;
static const long long SZ_Y    = (long long)ROWS*DI;

static const long long OFF_BIG = 0;
static const long long OFF_H   = OFF_BIG + SZ_BIG;
static const long long OFF_O   = OFF_H   + SZ_HB;
static const long long OFF_X   = OFF_O   + SZ_HB;
static const long long OFF_XBC = OFF_X   + SZ_HB;
static const long long OFF_DT  = OFF_XBC + SZ_XBC;
static const long long OFF_XDT = OFF_DT  + SZ_DT;
static const long long OFF_ACS = OFF_XDT + SZ_XDT;
static const long long OFF_CB  = OFF_ACS + SZ_ACS;
static const long long OFF_STA = OFF_CB  + SZ_CB;
static const long long OFF_SPR = OFF_STA + SZ_ST;
static const long long OFF_Y   = OFF_SPR + SZ_ST;
static const long long OFF_FF  = OFF_Y   + SZ_Y;
static const long long TOTALF  = OFF_FF  + SZ_Y;

__device__ float g_scratch[74842112]; // == TOTALF floats (~300 MB)

// ---------------- helpers ----------------
__device__ __forceinline__ float silu_f(float x) {
    return x / (1.f + __expf(-x));
}
__device__ __forceinline__ float softplus_f(float x) {
    return (x > 20.f) ? x : log1pf(__expf(x));
}
// split x into hi(bf16) + lo(bf16)
__device__ __forceinline__ void split_bf16(float x, __nv_bfloat16& hi, __nv_bfloat16& lo) {
    hi = __float2bfloat16_rn(x);
    lo = __float2bfloat16_rn(x - __bfloat162float(hi));
}
__device__ __forceinline__ uint32_t pack2(__nv_bfloat16 a, __nv_bfloat16 b) {
    __nv_bfloat162 h;
    h.x = a; h.y = b;
    return *(uint32_t*)&h;
}
__device__ __forceinline__ void mma_bf16(float* c, const uint32_t* a, const uint32_t* b) {
    asm volatile(
        "mma.sync.aligned.m16n8k16.row.col.f32.bf16.bf16.f32 "
        "{%0,%1,%2,%3}, {%4,%5,%6,%7}, {%8,%9}, {%0,%1,%2,%3};"
        : "+f"(c[0]), "+f"(c[1]), "+f"(c[2]), "+f"(c[3])
        : "r"(a[0]), "r"(a[1]), "r"(a[2]), "r"(a[3]), "r"(b[0]), "r"(b[1]));
}

// ---------------- bf16x2 split tensor-core NT GEMM ----------------
// C[M,N] = A[M,K] @ W[N,K]^T (+bias), fp32 in/out, ~16-bit effective mantissa.
// CTA tile 128x128, K-tile 32, 256 threads = 8 warps (2x4), warp tile 64x32.
// Requires: M % 128 == 0, K % 32 == 0, N even, rows 16B-aligned.
// SMEM rows hold 16 packed-k2 words, stride 20 (bank-conflict-free for quads).
#define SSTR 20
__global__ __launch_bounds__(256, 2)
void gemm_tc(const float* __restrict__ A, const float* __restrict__ W,
             const float* __restrict__ bias, float* __restrict__ C,
             int M, int N, int K, int lda, int ldw, int ldc,
             long long sA, long long sW, long long sC)
{
    A += (long long)blockIdx.z * sA;
    W += (long long)blockIdx.z * sW;
    C += (long long)blockIdx.z * sC;

    __shared__ uint32_t Ahi[128][SSTR];
    __shared__ uint32_t Alo[128][SSTR];
    __shared__ uint32_t Bhi[128][SSTR];
    __shared__ uint32_t Blo[128][SSTR];

    int bm = blockIdx.y * 128, bn = blockIdx.x * 128;
    int tid = threadIdx.x;
    int wid = tid >> 5, lane = tid & 31;
    int wm = (wid >> 2) * 64;          // 0 or 64
    int wn = (wid & 3) * 32;           // 0,32,64,96
    int lr = lane >> 2;                // 0..7
    int lc = lane & 3;                 // 0..3

    float acc[4][4][4];
    #pragma unroll
    for (int i = 0; i < 4; i++)
        #pragma unroll
        for (int j = 0; j < 4; j++)
            #pragma unroll
            for (int r = 0; r < 4; r++) acc[i][j][r] = 0.f;

    for (int k0 = 0; k0 < K; k0 += 32) {
        // stage A: 128 rows x 32 k (float4 -> 2 packed k2 words, hi+lo)
        #pragma unroll
        for (int i = 0; i < 4; i++) {
            int idx = tid + i * 256;
            int r = idx >> 3, c4 = (idx & 7) << 2;   // c4 in {0,4,...,28}
            const float4 v = *(const float4*)(A + (long long)(bm + r) * lda + k0 + c4);
            __nv_bfloat16 h0,l0,h1,l1,h2,l2,h3,l3;
            split_bf16(v.x, h0, l0); split_bf16(v.y, h1, l1);
            split_bf16(v.z, h2, l2); split_bf16(v.w, h3, l3);
            int c2 = c4 >> 1;
            Ahi[r][c2]     = pack2(h0, h1);
            Ahi[r][c2 + 1] = pack2(h2, h3);
            Alo[r][c2]     = pack2(l0, l1);
            Alo[r][c2 + 1] = pack2(l2, l3);
        }
        // stage W
        #pragma unroll
        for (int i = 0; i < 4; i++) {
            int idx = tid + i * 256;
            int r = idx >> 3, c4 = (idx & 7) << 2;
            int c2 = c4 >> 1;
            if (bn + r < N) {
                const float4 v = *(const float4*)(W + (long long)(bn + r) * ldw + k0 + c4);
                __nv_bfloat16 h0,l0,h1,l1,h2,l2,h3,l3;
                split_bf16(v.x, h0, l0); split_bf16(v.y, h1, l1);
                split_bf16(v.z, h2, l2); split_bf16(v.w, h3, l3);
                Bhi[r][c2]     = pack2(h0, h1);
                Bhi[r][c2 + 1] = pack2(h2, h3);
                Blo[r][c2]     = pack2(l0, l1);
                Blo[r][c2 + 1] = pack2(l2, l3);
            } else {
                Bhi[r][c2] = 0u; Bhi[r][c2 + 1] = 0u;
                Blo[r][c2] = 0u; Blo[r][c2 + 1] = 0u;
            }
        }
        __syncthreads();

        // two k16 steps per k-tile (kk2 = packed-k index base: 0, 8)
        #pragma unroll
        for (int kk2 = 0; kk2 < 16; kk2 += 8) {
            uint32_t ah[4][4], al[4][4], bh[4][2], bl[4][2];
            #pragma unroll
            for (int im = 0; im < 4; im++) {
                int r = wm + im * 16 + lr;
                ah[im][0] = Ahi[r][kk2 + lc];
                ah[im][1] = Ahi[r + 8][kk2 + lc];
                ah[im][2] = Ahi[r][kk2 + lc + 4];
                ah[im][3] = Ahi[r + 8][kk2 + lc + 4];
                al[im][0] = Alo[r][kk2 + lc];
                al[im][1] = Alo[r + 8][kk2 + lc];
                al[im][2] = Alo[r][kk2 + lc + 4];
                al[im][3] = Alo[r + 8][kk2 + lc + 4];
            }
            #pragma unroll
            for (int jn = 0; jn < 4; jn++) {
                int cdx = wn + jn * 8 + lr;
                bh[jn][0] = Bhi[cdx][kk2 + lc];
                bh[jn][1] = Bhi[cdx][kk2 + lc + 4];
                bl[jn][0] = Blo[cdx][kk2 + lc];
                bl[jn][1] = Blo[cdx][kk2 + lc + 4];
            }
            #pragma unroll
            for (int im = 0; im < 4; im++)
                #pragma unroll
                for (int jn = 0; jn < 4; jn++) {
                    mma_bf16(acc[im][jn], ah[im], bl[jn]);   // hi*lo
                    mma_bf16(acc[im][jn], al[im], bh[jn]);   // lo*hi
                    mma_bf16(acc[im][jn], ah[im], bh[jn]);   // hi*hi
                }
        }
        __syncthreads();
    }

    // store (M multiple of 128; guard N)
    #pragma unroll
    for (int im = 0; im < 4; im++) {
        #pragma unroll
        for (int jn = 0; jn < 4; jn++) {
            int gm = bm + wm + im * 16 + lr;
            int gc = bn + wn + jn * 8 + 2 * lc;
            if (gc < N) {
                float b0 = bias ? bias[gc] : 0.f;
                float b1 = bias ? bias[gc + 1] : 0.f;
                float* p0 = C + (long long)gm * ldc + gc;
                p0[0] = acc[im][jn][0] + b0;
                p0[1] = acc[im][jn][1] + b1;
                float* p1 = C + (long long)(gm + 8) * ldc + gc;
                p1[0] = acc[im][jn][2] + b0;
                p1[1] = acc[im][jn][3] + b1;
            }
        }
    }
}

// ---------------- rmsnorm: out = rmsnorm(a + alpha*b, w) ----------------
__global__ void rmsnorm_kernel(const float* __restrict__ a, const float* __restrict__ b,
                               float alpha, const float* __restrict__ w,
                               float* __restrict__ out, int D)
{
    long long row = blockIdx.x;
    const float* ap = a + row * D;
    const float* bp = b ? (b + row * D) : nullptr;
    int per = D >> 8;
    float v[8];
    float ss = 0.f;
    for (int j = 0; j < per; j++) {
        int i = threadIdx.x + j * 256;
        float x = ap[i] + (bp ? alpha * bp[i] : 0.f);
        v[j] = x;
        ss += x * x;
    }
    __shared__ float red[256];
    red[threadIdx.x] = ss;
    __syncthreads();
    for (int off = 128; off; off >>= 1) {
        if (threadIdx.x < off) red[threadIdx.x] += red[threadIdx.x + off];
        __syncthreads();
    }
    float scale = rsqrtf(red[0] / D + EPSN);
    float* op = out + row * D;
    for (int j = 0; j < per; j++) {
        int i = threadIdx.x + j * 256;
        op[i] = v[j] * scale * w[i];
    }
}

// ---------------- gated rmsnorm ----------------
__global__ void gated_rmsnorm_kernel(const float* __restrict__ y, const float* __restrict__ z,
                                     int ldz, const float* __restrict__ w,
                                     float* __restrict__ out)
{
    long long row = blockIdx.x;
    const float* yp = y + row * DI;
    const float* zp = z + row * (long long)ldz;
    float v[8];
    float ss = 0.f;
    #pragma unroll
    for (int j = 0; j < 8; j++) {
        int i = threadIdx.x + j * 256;
        float x = yp[i] * silu_f(zp[i]);
        v[j] = x;
        ss += x * x;
    }
    __shared__ float red[256];
    red[threadIdx.x] = ss;
    __syncthreads();
    for (int off = 128; off; off >>= 1) {
        if (threadIdx.x < off) red[threadIdx.x] += red[threadIdx.x + off];
        __syncthreads();
    }
    float scale = rsqrtf(red[0] / DI + EPSN);
    float* op = out + row * DI;
    #pragma unroll
    for (int j = 0; j < 8; j++) {
        int i = threadIdx.x + j * 256;
        op[i] = v[j] * scale * w[i];
    }
}

// ---------------- flash attention (non-causal) ----------------
__global__ void attn_kernel(const float* __restrict__ qkv, float* __restrict__ o)
{
    __shared__ float Ksh[64][64];
    __shared__ float Vsh[64][64];
    int bh = blockIdx.y;
    int b = bh >> 4, h = bh & 15;
    int l = blockIdx.x * 64 + threadIdx.x;
    const float* qp = qkv + ((long long)(b * L_ + l) * 3072) + h * 64;
    float q[64], acc[64];
    #pragma unroll
    for (int d = 0; d < 64; d++) { q[d] = qp[d] * 0.125f; acc[d] = 0.f; }
    float m = -1e30f, lsum = 0.f;
    for (int kt = 0; kt < L_ / 64; kt++) {
        const float* kb = qkv + ((long long)(b * L_ + kt * 64) * 3072) + 1024 + h * 64;
        const float* vb = kb + 1024;
        for (int r = 0; r < 64; r++) {
            Ksh[r][threadIdx.x] = kb[(long long)r * 3072 + threadIdx.x];
            Vsh[r][threadIdx.x] = vb[(long long)r * 3072 + threadIdx.x];
        }
        __syncthreads();
        for (int j = 0; j < 64; j++) {
            float s = 0.f;
            #pragma unroll
            for (int d = 0; d < 64; d++) s += q[d] * Ksh[j][d];
            float p;
            if (s > m) {
                float corr = __expf(m - s);
                #pragma unroll
                for (int d = 0; d < 64; d++) acc[d] *= corr;
                lsum *= corr;
                m = s;
                p = 1.f;
            } else {
                p = __expf(s - m);
            }
            lsum += p;
            #pragma unroll
            for (int d = 0; d < 64; d++) acc[d] += p * Vsh[j][d];
        }
        __syncthreads();
    }
    float inv = 1.f / lsum;
    float* op = o + ((long long)(b * L_ + l) * DM) + h * 64;
    #pragma unroll
    for (int d = 0; d < 64; d++) op[d] = acc[d] * inv;
}

// ---------------- depthwise causal conv (k=4) + bias + silu ----------------
__global__ void conv_kernel(const float* __restrict__ zx, const float* __restrict__ cw,
                            const float* __restrict__ cb, float* __restrict__ xbc)
{
    int idx = blockIdx.x * 256 + threadIdx.x;
    if (idx >= B_ * L_ * CONVD) return;
    int c = idx % CONVD;
    int t = (idx / CONVD) % L_;
    int b = idx / (CONVD * L_);
    float s = cb[c];
    #pragma unroll
    for (int k = 0; k < 4; k++) {
        int tt = t - 3 + k;
        if (tt >= 0)
            s += zx[((long long)(b * L_ + tt) * DINP) + DI + c] * cw[c * 4 + k];
    }
    xbc[idx] = silu_f(s);
}

// ---------------- dt (softplus) and xdt = xs*dt ----------------
__global__ void dtxdt_kernel(const float* __restrict__ zx, const float* __restrict__ xbc,
                             const float* __restrict__ dt_bias,
                             float* __restrict__ dtb, float* __restrict__ xdt)
{
    int idx = blockIdx.x * 256 + threadIdx.x;
    if (idx >= ROWS * DI) return;
    int p = idx & 63;
    int h = (idx >> 6) & 31;
    long long row = idx >> 11;
    float raw = zx[row * DINP + DI + CONVD + h] + dt_bias[h];
    float d = softplus_f(raw);
    xdt[idx] = xbc[row * CONVD + h * 64 + p] * d;
    if (p == 0) dtb[row * HS + h] = d;
}

// ---------------- per-chunk inclusive cumsum ----------------
__global__ void cumsum_kernel(const float* __restrict__ dtb, const float* __restrict__ A_log,
                              float* __restrict__ Acs)
{
    __shared__ float s[256];
    int blk = blockIdx.x;
    int ck = blk & 7;
    int bh = blk >> 3;
    int h = bh & 31;
    int b = bh >> 5;
    int l = threadIdx.x;
    int gl = ck * 256 + l;
    float a = -__expf(A_log[h]) * dtb[((long long)(b * L_ + gl)) * HS + h];
    s[l] = a;
    __syncthreads();
    for (int off = 1; off < 256; off <<= 1) {
        float t = (l >= off) ? s[l - off] : 0.f;
        __syncthreads();
        s[l] += t;
        __syncthreads();
    }
    Acs[(long long)bh * L_ + gl] = s[l];
}

// ---------------- chunk states ----------------
__global__ void states_kernel(const float* __restrict__ xbc, const float* __restrict__ xdt,
                              const float* __restrict__ Acs, float* __restrict__ states)
{
    __shared__ float xs_sh[8][64];
    __shared__ float dec[256];
    int blk = blockIdx.x;
    int ck = blk & 7;
    int bh = blk >> 3;
    int h = bh & 31;
    int b = bh >> 5;
    int n = threadIdx.x;
    const float* acs = Acs + (long long)bh * L_ + ck * 256;
    float aLast = acs[255];
    for (int i = n; i < 256; i += 128) dec[i] = __expf(aLast - acs[i]);
    float acc[64];
    #pragma unroll
    for (int p = 0; p < 64; p++) acc[p] = 0.f;
    long long rowbase = (long long)(b * L_ + ck * 256);
    for (int lt = 0; lt < 32; lt++) {
        __syncthreads();
        #pragma unroll
        for (int i = 0; i < 4; i++) {
            int idx = n + i * 128;
            int r = idx >> 6, p = idx & 63;
            xs_sh[r][p] = xdt[(rowbase + lt * 8 + r) * DI + h * 64 + p];
        }
        __syncthreads();
        #pragma unroll
        for (int r = 0; r < 8; r++) {
            int l = lt * 8 + r;
            float w = xbc[(rowbase + l) * CONVD + DI + n] * dec[l];
            #pragma unroll
            for (int p = 0; p < 64; p++) acc[p] += w * xs_sh[r][p];
        }
    }
    float* op = states + ((long long)(bh * NC + ck) * NST + n) * P_;
    #pragma unroll
    for (int p = 0; p < 64; p++) op[p] = acc[p];
}

// ---------------- inter-chunk scan ----------------
__global__ void scan_kernel(const float* __restrict__ states, const float* __restrict__ Acs,
                            float* __restrict__ Sprev)
{
    int bh = blockIdx.x;
    int tid = threadIdx.x;
    float S[32];
    #pragma unroll
    for (int j = 0; j < 32; j++) S[j] = 0.f;
    for (int c = 0; c < NC; c++) {
        float dc = __expf(Acs[(long long)bh * L_ + c * 256 + 255]);
        const float* sp = states + (long long)(bh * NC + c) * 8192;
        float* pp = Sprev + (long long)(bh * NC + c) * 8192;
        #pragma unroll
        for (int j = 0; j < 32; j++) {
            int idx = tid + j * 256;
            pp[idx] = S[j];
            S[j] = S[j] * dc + sp[idx];
        }
    }
}

// ---------------- Y: diag + off-diag + D*xs ----------------
__global__ void y_kernel(const float* __restrict__ xbc, const float* __restrict__ xdt,
                         const float* __restrict__ Acs, const float* __restrict__ CB,
                         const float* __restrict__ Sprev, const float* __restrict__ Dv,
                         float* __restrict__ Y)
{
    __shared__ float sh[128 * 64];
    __shared__ float acs_sh[256];
    int blk = blockIdx.x;
    int ck = blk & 7;
    int bh = blk >> 3;
    int h = bh & 31;
    int b = bh >> 5;
    int l = threadIdx.x;
    int gl = ck * 256 + l;
    long long row = (long long)(b * L_ + gl);

    acs_sh[l] = Acs[(long long)bh * L_ + gl];
    const float* spv = Sprev + (long long)(bh * NC + ck) * 8192;
    #pragma unroll
    for (int j = 0; j < 32; j++) sh[l + j * 256] = spv[l + j * 256];
    __syncthreads();

    float aL = acs_sh[l];
    float y[64];
    #pragma unroll
    for (int p = 0; p < 64; p++) y[p] = 0.f;

    {
        float eA = __expf(aL);
        const float* cp = xbc + row * CONVD + DI + NST;
        for (int n = 0; n < 128; n++) {
            float cn = cp[n] * eA;
            const float* sr = &sh[n * 64];
            #pragma unroll
            for (int p = 0; p < 64; p++) y[p] += cn * sr[p];
        }
    }

    const float* cbp = CB + (long long)(b * NC + ck) * (CH * CH);
    long long rowbase = (long long)(b * L_ + ck * 256);
    for (int st = 0; st < 4; st++) {
        __syncthreads();
        #pragma unroll
        for (int j = 0; j < 16; j++) {
            int idx = l + j * 256;
            int r = idx >> 6, p = idx & 63;
            sh[r * 64 + p] = xdt[(rowbase + st * 64 + r) * DI + h * 64 + p];
        }
        __syncthreads();
        for (int r = 0; r < 64; r++) {
            int s = st * 64 + r;
            if (s <= l) {
                float w = cbp[s * 256 + l] * __expf(aL - acs_sh[s]);
                const float* xr = &sh[r * 64];
                #pragma unroll
                for (int p = 0; p < 64; p++) y[p] += w * xr[p];
            }
        }
    }

    float Dh = Dv[h];
    const float* xsrow = xbc + row * CONVD + h * 64;
    float* op = Y + row * DI + h * 64;
    #pragma unroll
    for (int p = 0; p < 64; p++) op[p] = y[p] + Dh * xsrow[p];
}

// ---------------- swiglu ----------------
__global__ void swiglu_kernel(const float* __restrict__ y, float* __restrict__ ff)
{
    int idx = blockIdx.x * 256 + threadIdx.x;
    if (idx >= ROWS * DFF) return;
    long long row = idx / DFF;
    int f = idx % DFF;
    const float* yp = y + row * (2 * DFF);
    ff[idx] = yp[f] * silu_f(yp[f + DFF]);
}

// ---------------- host launcher ----------------
extern "C" void kernel_launch(void* const* d_in, const int* in_sizes, int n_in,
                              void* d_out, int out_size)
{
    const float* x_in       = (const float*)d_in[0];
    const float* attn_norm  = (const float*)d_in[1];
    const float* Wqkv       = (const float*)d_in[2];
    const float* Wqkv_b     = (const float*)d_in[3];
    const float* attn_out_w = (const float*)d_in[4];
    const float* attn_out_b = (const float*)d_in[5];
    const float* normf_w    = (const float*)d_in[6];
    const float* m_in_w     = (const float*)d_in[7];
    const float* m_conv_w   = (const float*)d_in[8];
    const float* m_conv_b   = (const float*)d_in[9];
    const float* m_dt_bias  = (const float*)d_in[10];
    const float* m_A_log    = (const float*)d_in[11];
    const float* m_D        = (const float*)d_in[12];
    const float* m_norm_w   = (const float*)d_in[13];
    const float* m_out_w    = (const float*)d_in[14];
    const float* fc1_w      = (const float*)d_in[15];
    const float* fc2_w      = (const float*)d_in[16];
    const float* final_norm = (const float*)d_in[17];
    float* out = (float*)d_out;

    float* scr = nullptr;
    cudaGetSymbolAddress((void**)&scr, g_scratch);

    float* bBIG = scr + OFF_BIG;
    float* bH   = scr + OFF_H;
    float* bO   = scr + OFF_O;
    float* bX   = scr + OFF_X;
    float* bXBC = scr + OFF_XBC;
    float* bDT  = scr + OFF_DT;
    float* bXDT = scr + OFF_XDT;
    float* bACS = scr + OFF_ACS;
    float* bCB  = scr + OFF_CB;
    float* bSTA = scr + OFF_STA;
    float* bSPR = scr + OFF_SPR;
    float* bY   = scr + OFF_Y;
    float* bFF  = scr + OFF_FF;

    // ---- attention block ----
    rmsnorm_kernel<<<ROWS, 256>>>(x_in, nullptr, 0.f, attn_norm, bH, DM);
    gemm_tc<<<dim3(3072/128, ROWS/128, 1), 256>>>(bH, Wqkv, Wqkv_b, bBIG,
        ROWS, 3072, DM, DM, DM, 3072, 0, 0, 0);
    attn_kernel<<<dim3(L_/64, B_*NH), 64>>>(bBIG, bO);
    gemm_tc<<<dim3(DM/128, ROWS/128, 1), 256>>>(bO, attn_out_w, attn_out_b, bH,
        ROWS, DM, DM, DM, DM, DM, 0, 0, 0);
    rmsnorm_kernel<<<ROWS, 256>>>(bH, x_in, 1.f, normf_w, bX, DM);

    // ---- mamba layers ----
    for (int i = 0; i < 4; i++) {
        const float* in_w   = m_in_w   + (long long)i * DINP * DM;
        const float* conv_w = m_conv_w + (long long)i * CONVD * 4;
        const float* conv_b = m_conv_b + (long long)i * CONVD;
        const float* dtbias = m_dt_bias+ (long long)i * HS;
        const float* Alog   = m_A_log  + (long long)i * HS;
        const float* Dv     = m_D      + (long long)i * HS;
        const float* nw     = m_norm_w + (long long)i * DI;
        const float* ow     = m_out_w  + (long long)i * DM * DI;

        gemm_tc<<<dim3((DINP+127)/128, ROWS/128, 1), 256>>>(bX, in_w, nullptr, bBIG,
            ROWS, DINP, DM, DM, DM, DINP, 0, 0, 0);
        conv_kernel<<<(ROWS*CONVD)/256, 256>>>(bBIG, conv_w, conv_b, bXBC);
        dtxdt_kernel<<<(ROWS*DI)/256, 256>>>(bBIG, bXBC, dtbias, bDT, bXDT);
        cumsum_kernel<<<B_*HS*NC, 256>>>(bDT, Alog, bACS);
        // CB[b,c][s][l] = Bm[s] . Cm[l]  (batched over b*c = 16)
        gemm_tc<<<dim3(2, 2, B_*NC), 256>>>(
            bXBC + DI, bXBC + DI + NST, nullptr, bCB,
            CH, CH, NST, CONVD, CONVD, CH,
            (long long)CH * CONVD, (long long)CH * CONVD, (long long)CH * CH);
        states_kernel<<<B_*HS*NC, 128>>>(bXBC, bXDT, bACS, bSTA);
        scan_kernel<<<B_*HS, 256>>>(bSTA, bACS, bSPR);
        y_kernel<<<B_*HS*NC, 256>>>(bXBC, bXDT, bACS, bCB, bSPR, Dv, bY);
        gated_rmsnorm_kernel<<<ROWS, 256>>>(bY, bBIG, DINP, nw, bY);
        gemm_tc<<<dim3(DM/128, ROWS/128, 1), 256>>>(bY, ow, nullptr, bX,
            ROWS, DM, DI, DI, DI, DM, 0, 0, 0);
    }

    // ---- MLP + final norm ----
    gemm_tc<<<dim3((2*DFF)/128, ROWS/128, 1), 256>>>(bX, fc1_w, nullptr, bBIG,
        ROWS, 2*DFF, DM, DM, DM, 2*DFF, 0, 0, 0);
    swiglu_kernel<<<(ROWS*DFF)/256, 256>>>(bBIG, bFF);
    gemm_tc<<<dim3(DM/128, ROWS/128, 1), 256>>>(bFF, fc2_w, nullptr, bH,
        ROWS, DM, DFF, DFF, DFF, DM, 0, 0, 0);
    rmsnorm_kernel<<<ROWS, 256>>>(bH, bX, ALPHA, final_norm, out, DM);
}

// round 4
// speedup vs baseline: 2.0805x; 1.0977x over previous
#include <cuda_runtime.h>
#include <cuda_bf16.h>
#include <math.h>
#include <stdint.h>

// ---------------- constants ----------------
#define B_   2
#define L_   2048
#define DM   1024          // D_MODEL
#define NH   16            // NHEAD
#define HD   64            // HD_ATT
#define DI   2048          // D_INNER
#define HS   32            // H_SSM
#define P_   64            // HEADDIM
#define NST  128           // D_STATE
#define CONVD 2304         // CONV_DIM
#define DINP 4384          // D_IN_PROJ
#define CH   256           // CHUNK
#define NC   8             // L/CHUNK
#define DFF  2048
#define ALPHA 1.68f
#define EPSN 1e-5f

#define ROWS (B_*L_)       // 4096

// ---------------- scratch ----------------
static const long long SZ_BIG  = (long long)ROWS*DINP;
static const long long SZ_HB   = (long long)ROWS*DM;
static const long long SZ_XBC  = (long long)ROWS*CONVD;
static const long long SZ_DT   = (long long)ROWS*HS;
static const long long SZ_XDT  = (long long)ROWS*DI;
static const long long SZ_ACS  = (long long)B_*HS*L_;
static const long long SZ_CB   = (long long)B_*NC*CH*CH;
static const long long SZ_ST   = (long long)B_*HS*NC*NST*P_;
static const long long SZ_Y    = (long long)ROWS*DI;

static const long long OFF_BIG = 0;
static const long long OFF_H   = OFF_BIG + SZ_BIG;
static const long long OFF_O   = OFF_H   + SZ_HB;
static const long long OFF_X   = OFF_O   + SZ_HB;
static const long long OFF_XBC = OFF_X   + SZ_HB;
static const long long OFF_DT  = OFF_XBC + SZ_XBC;
static const long long OFF_XDT = OFF_DT  + SZ_DT;
static const long long OFF_ACS = OFF_XDT + SZ_XDT;
static const long long OFF_CB  = OFF_ACS + SZ_ACS;
static const long long OFF_STA = OFF_CB  + SZ_CB;
static const long long OFF_SPR = OFF_STA + SZ_ST;
static const long long OFF_Y   = OFF_SPR + SZ_ST;
static const long long OFF_FF  = OFF_Y   + SZ_Y;
static const long long TOTALF  = OFF_FF  + SZ_Y;

__device__ float g_scratch[74842112]; // == TOTALF floats (~300 MB)

// ---------------- helpers ----------------
__device__ __forceinline__ float silu_f(float x) {
    return x / (1.f + __expf(-x));
}
__device__ __forceinline__ float softplus_f(float x) {
    return (x > 20.f) ? x : log1pf(__expf(x));
}
// split x into hi(bf16) + lo(bf16)
__device__ __forceinline__ void split_bf16(float x, __nv_bfloat16& hi, __nv_bfloat16& lo) {
    hi = __float2bfloat16_rn(x);
    lo = __float2bfloat16_rn(x - __bfloat162float(hi));
}
__device__ __forceinline__ uint32_t pack2(__nv_bfloat16 a, __nv_bfloat16 b) {
    __nv_bfloat162 h;
    h.x = a; h.y = b;
    return *(uint32_t*)&h;
}
__device__ __forceinline__ void mma_bf16(float* c, const uint32_t* a, const uint32_t* b) {
    asm volatile(
        "mma.sync.aligned.m16n8k16.row.col.f32.bf16.bf16.f32 "
        "{%0,%1,%2,%3}, {%4,%5,%6,%7}, {%8,%9}, {%0,%1,%2,%3};"
        : "+f"(c[0]), "+f"(c[1]), "+f"(c[2]), "+f"(c[3])
        : "r"(a[0]), "r"(a[1]), "r"(a[2]), "r"(a[3]), "r"(b[0]), "r"(b[1]));
}

// ---------------- bf16x2 split tensor-core NT GEMM, register-prefetch pipelined ----------------
// C[M,N] = A[M,K] @ W[N,K]^T (+bias), fp32 in/out, ~16-bit effective mantissa.
// CTA tile 128x128, K-tile 32, 256 threads = 8 warps (2x4), warp tile 64x32.
// Requires: M % 128 == 0, K % 32 == 0, N even, rows 16B-aligned.
#define SSTR 20
__global__ __launch_bounds__(256, 2)
void gemm_tc(const float* __restrict__ A, const float* __restrict__ W,
             const float* __restrict__ bias, float* __restrict__ C,
             int M, int N, int K, int lda, int ldw, int ldc,
             long long sA, long long sW, long long sC)
{
    A += (long long)blockIdx.z * sA;
    W += (long long)blockIdx.z * sW;
    C += (long long)blockIdx.z * sC;

    __shared__ uint32_t Ahi[128][SSTR];
    __shared__ uint32_t Alo[128][SSTR];
    __shared__ uint32_t Bhi[128][SSTR];
    __shared__ uint32_t Blo[128][SSTR];

    int bm = blockIdx.y * 128, bn = blockIdx.x * 128;
    int tid = threadIdx.x;
    int wid = tid >> 5, lane = tid & 31;
    int wm = (wid >> 2) * 64;          // 0 or 64
    int wn = (wid & 3) * 32;           // 0,32,64,96
    int lr = lane >> 2;                // 0..7
    int lc = lane & 3;                 // 0..3

    // per-thread staging coordinates (same for all 4 chunks; chunk i adds i*32 rows)
    int sr = tid >> 3;                 // row 0..31 within 32-row group
    int sc4 = (tid & 7) << 2;          // k-offset 0,4,...,28
    int sc2 = sc4 >> 1;                // packed-word offset

    float acc[4][4][4];
    #pragma unroll
    for (int i = 0; i < 4; i++)
        #pragma unroll
        for (int j = 0; j < 4; j++)
            #pragma unroll
            for (int r = 0; r < 4; r++) acc[i][j][r] = 0.f;

    // ---- prefetch first k-tile into registers ----
    float4 pa[4], pw[4];
    #pragma unroll
    for (int i = 0; i < 4; i++) {
        int r = sr + i * 32;
        pa[i] = *(const float4*)(A + (long long)(bm + r) * lda + sc4);
        if (bn + r < N) pw[i] = *(const float4*)(W + (long long)(bn + r) * ldw + sc4);
        else            pw[i] = make_float4(0.f, 0.f, 0.f, 0.f);
    }

    for (int k0 = 0; k0 < K; k0 += 32) {
        // ---- convert + store staged registers to SMEM ----
        #pragma unroll
        for (int i = 0; i < 4; i++) {
            int r = sr + i * 32;
            __nv_bfloat16 h0,l0,h1,l1,h2,l2,h3,l3;
            split_bf16(pa[i].x, h0, l0); split_bf16(pa[i].y, h1, l1);
            split_bf16(pa[i].z, h2, l2); split_bf16(pa[i].w, h3, l3);
            Ahi[r][sc2]     = pack2(h0, h1);
            Ahi[r][sc2 + 1] = pack2(h2, h3);
            Alo[r][sc2]     = pack2(l0, l1);
            Alo[r][sc2 + 1] = pack2(l2, l3);
            split_bf16(pw[i].x, h0, l0); split_bf16(pw[i].y, h1, l1);
            split_bf16(pw[i].z, h2, l2); split_bf16(pw[i].w, h3, l3);
            Bhi[r][sc2]     = pack2(h0, h1);
            Bhi[r][sc2 + 1] = pack2(h2, h3);
            Blo[r][sc2]     = pack2(l0, l1);
            Blo[r][sc2 + 1] = pack2(l2, l3);
        }
        __syncthreads();

        // ---- issue prefetch LDGs for the next k-tile (latency hidden by MMAs) ----
        if (k0 + 32 < K) {
            int kn = k0 + 32;
            #pragma unroll
            for (int i = 0; i < 4; i++) {
                int r = sr + i * 32;
                pa[i] = *(const float4*)(A + (long long)(bm + r) * lda + kn + sc4);
                if (bn + r < N) pw[i] = *(const float4*)(W + (long long)(bn + r) * ldw + kn + sc4);
                else            pw[i] = make_float4(0.f, 0.f, 0.f, 0.f);
            }
        }

        // ---- MMAs on current SMEM tile ----
        #pragma unroll
        for (int kk2 = 0; kk2 < 16; kk2 += 8) {
            uint32_t bh[4][2], bl[4][2];
            #pragma unroll
            for (int jn = 0; jn < 4; jn++) {
                int cdx = wn + jn * 8 + lr;
                bh[jn][0] = Bhi[cdx][kk2 + lc];
                bh[jn][1] = Bhi[cdx][kk2 + lc + 4];
                bl[jn][0] = Blo[cdx][kk2 + lc];
                bl[jn][1] = Blo[cdx][kk2 + lc + 4];
            }
            #pragma unroll
            for (int im = 0; im < 4; im++) {
                int r = wm + im * 16 + lr;
                uint32_t ah[4], al[4];
                ah[0] = Ahi[r][kk2 + lc];
                ah[1] = Ahi[r + 8][kk2 + lc];
                ah[2] = Ahi[r][kk2 + lc + 4];
                ah[3] = Ahi[r + 8][kk2 + lc + 4];
                al[0] = Alo[r][kk2 + lc];
                al[1] = Alo[r + 8][kk2 + lc];
                al[2] = Alo[r][kk2 + lc + 4];
                al[3] = Alo[r + 8][kk2 + lc + 4];
                #pragma unroll
                for (int jn = 0; jn < 4; jn++) {
                    mma_bf16(acc[im][jn], ah, bl[jn]);   // hi*lo
                    mma_bf16(acc[im][jn], al, bh[jn]);   // lo*hi
                    mma_bf16(acc[im][jn], ah, bh[jn]);   // hi*hi
                }
            }
        }
        __syncthreads();
    }

    // store (M multiple of 128; guard N)
    #pragma unroll
    for (int im = 0; im < 4; im++) {
        #pragma unroll
        for (int jn = 0; jn < 4; jn++) {
            int gm = bm + wm + im * 16 + lr;
            int gc = bn + wn + jn * 8 + 2 * lc;
            if (gc < N) {
                float b0 = bias ? bias[gc] : 0.f;
                float b1 = bias ? bias[gc + 1] : 0.f;
                float* p0 = C + (long long)gm * ldc + gc;
                p0[0] = acc[im][jn][0] + b0;
                p0[1] = acc[im][jn][1] + b1;
                float* p1 = C + (long long)(gm + 8) * ldc + gc;
                p1[0] = acc[im][jn][2] + b0;
                p1[1] = acc[im][jn][3] + b1;
            }
        }
    }
}

// ---------------- rmsnorm: out = rmsnorm(a + alpha*b, w) ----------------
__global__ void rmsnorm_kernel(const float* __restrict__ a, const float* __restrict__ b,
                               float alpha, const float* __restrict__ w,
                               float* __restrict__ out, int D)
{
    long long row = blockIdx.x;
    const float* ap = a + row * D;
    const float* bp = b ? (b + row * D) : nullptr;
    int per = D >> 8;
    float v[8];
    float ss = 0.f;
    for (int j = 0; j < per; j++) {
        int i = threadIdx.x + j * 256;
        float x = ap[i] + (bp ? alpha * bp[i] : 0.f);
        v[j] = x;
        ss += x * x;
    }
    __shared__ float red[256];
    red[threadIdx.x] = ss;
    __syncthreads();
    for (int off = 128; off; off >>= 1) {
        if (threadIdx.x < off) red[threadIdx.x] += red[threadIdx.x + off];
        __syncthreads();
    }
    float scale = rsqrtf(red[0] / D + EPSN);
    float* op = out + row * D;
    for (int j = 0; j < per; j++) {
        int i = threadIdx.x + j * 256;
        op[i] = v[j] * scale * w[i];
    }
}

// ---------------- gated rmsnorm ----------------
__global__ void gated_rmsnorm_kernel(const float* __restrict__ y, const float* __restrict__ z,
                                     int ldz, const float* __restrict__ w,
                                     float* __restrict__ out)
{
    long long row = blockIdx.x;
    const float* yp = y + row * DI;
    const float* zp = z + row * (long long)ldz;
    float v[8];
    float ss = 0.f;
    #pragma unroll
    for (int j = 0; j < 8; j++) {
        int i = threadIdx.x + j * 256;
        float x = yp[i] * silu_f(zp[i]);
        v[j] = x;
        ss += x * x;
    }
    __shared__ float red[256];
    red[threadIdx.x] = ss;
    __syncthreads();
    for (int off = 128; off; off >>= 1) {
        if (threadIdx.x < off) red[threadIdx.x] += red[threadIdx.x + off];
        __syncthreads();
    }
    float scale = rsqrtf(red[0] / DI + EPSN);
    float* op = out + row * DI;
    #pragma unroll
    for (int j = 0; j < 8; j++) {
        int i = threadIdx.x + j * 256;
        op[i] = v[j] * scale * w[i];
    }
}

// ---------------- flash attention (non-causal) ----------------
__global__ void attn_kernel(const float* __restrict__ qkv, float* __restrict__ o)
{
    __shared__ float Ksh[64][64];
    __shared__ float Vsh[64][64];
    int bh = blockIdx.y;
    int b = bh >> 4, h = bh & 15;
    int l = blockIdx.x * 64 + threadIdx.x;
    const float* qp = qkv + ((long long)(b * L_ + l) * 3072) + h * 64;
    float q[64], acc[64];
    #pragma unroll
    for (int d = 0; d < 64; d++) { q[d] = qp[d] * 0.125f; acc[d] = 0.f; }
    float m = -1e30f, lsum = 0.f;
    for (int kt = 0; kt < L_ / 64; kt++) {
        const float* kb = qkv + ((long long)(b * L_ + kt * 64) * 3072) + 1024 + h * 64;
        const float* vb = kb + 1024;
        for (int r = 0; r < 64; r++) {
            Ksh[r][threadIdx.x] = kb[(long long)r * 3072 + threadIdx.x];
            Vsh[r][threadIdx.x] = vb[(long long)r * 3072 + threadIdx.x];
        }
        __syncthreads();
        for (int j = 0; j < 64; j++) {
            float s = 0.f;
            #pragma unroll
            for (int d = 0; d < 64; d++) s += q[d] * Ksh[j][d];
            float p;
            if (s > m) {
                float corr = __expf(m - s);
                #pragma unroll
                for (int d = 0; d < 64; d++) acc[d] *= corr;
                lsum *= corr;
                m = s;
                p = 1.f;
            } else {
                p = __expf(s - m);
            }
            lsum += p;
            #pragma unroll
            for (int d = 0; d < 64; d++) acc[d] += p * Vsh[j][d];
        }
        __syncthreads();
    }
    float inv = 1.f / lsum;
    float* op = o + ((long long)(b * L_ + l) * DM) + h * 64;
    #pragma unroll
    for (int d = 0; d < 64; d++) op[d] = acc[d] * inv;
}

// ---------------- depthwise causal conv (k=4) + bias + silu ----------------
__global__ void conv_kernel(const float* __restrict__ zx, const float* __restrict__ cw,
                            const float* __restrict__ cb, float* __restrict__ xbc)
{
    int idx = blockIdx.x * 256 + threadIdx.x;
    if (idx >= B_ * L_ * CONVD) return;
    int c = idx % CONVD;
    int t = (idx / CONVD) % L_;
    int b = idx / (CONVD * L_);
    float s = cb[c];
    #pragma unroll
    for (int k = 0; k < 4; k++) {
        int tt = t - 3 + k;
        if (tt >= 0)
            s += zx[((long long)(b * L_ + tt) * DINP) + DI + c] * cw[c * 4 + k];
    }
    xbc[idx] = silu_f(s);
}

// ---------------- dt (softplus) and xdt = xs*dt ----------------
__global__ void dtxdt_kernel(const float* __restrict__ zx, const float* __restrict__ xbc,
                             const float* __restrict__ dt_bias,
                             float* __restrict__ dtb, float* __restrict__ xdt)
{
    int idx = blockIdx.x * 256 + threadIdx.x;
    if (idx >= ROWS * DI) return;
    int p = idx & 63;
    int h = (idx >> 6) & 31;
    long long row = idx >> 11;
    float raw = zx[row * DINP + DI + CONVD + h] + dt_bias[h];
    float d = softplus_f(raw);
    xdt[idx] = xbc[row * CONVD + h * 64 + p] * d;
    if (p == 0) dtb[row * HS + h] = d;
}

// ---------------- per-chunk inclusive cumsum ----------------
__global__ void cumsum_kernel(const float* __restrict__ dtb, const float* __restrict__ A_log,
                              float* __restrict__ Acs)
{
    __shared__ float s[256];
    int blk = blockIdx.x;
    int ck = blk & 7;
    int bh = blk >> 3;
    int h = bh & 31;
    int b = bh >> 5;
    int l = threadIdx.x;
    int gl = ck * 256 + l;
    float a = -__expf(A_log[h]) * dtb[((long long)(b * L_ + gl)) * HS + h];
    s[l] = a;
    __syncthreads();
    for (int off = 1; off < 256; off <<= 1) {
        float t = (l >= off) ? s[l - off] : 0.f;
        __syncthreads();
        s[l] += t;
        __syncthreads();
    }
    Acs[(long long)bh * L_ + gl] = s[l];
}

// ---------------- chunk states ----------------
__global__ void states_kernel(const float* __restrict__ xbc, const float* __restrict__ xdt,
                              const float* __restrict__ Acs, float* __restrict__ states)
{
    __shared__ float xs_sh[8][64];
    __shared__ float dec[256];
    int blk = blockIdx.x;
    int ck = blk & 7;
    int bh = blk >> 3;
    int h = bh & 31;
    int b = bh >> 5;
    int n = threadIdx.x;
    const float* acs = Acs + (long long)bh * L_ + ck * 256;
    float aLast = acs[255];
    for (int i = n; i < 256; i += 128) dec[i] = __expf(aLast - acs[i]);
    float acc[64];
    #pragma unroll
    for (int p = 0; p < 64; p++) acc[p] = 0.f;
    long long rowbase = (long long)(b * L_ + ck * 256);
    for (int lt = 0; lt < 32; lt++) {
        __syncthreads();
        #pragma unroll
        for (int i = 0; i < 4; i++) {
            int idx = n + i * 128;
            int r = idx >> 6, p = idx & 63;
            xs_sh[r][p] = xdt[(rowbase + lt * 8 + r) * DI + h * 64 + p];
        }
        __syncthreads();
        #pragma unroll
        for (int r = 0; r < 8; r++) {
            int l = lt * 8 + r;
            float w = xbc[(rowbase + l) * CONVD + DI + n] * dec[l];
            #pragma unroll
            for (int p = 0; p < 64; p++) acc[p] += w * xs_sh[r][p];
        }
    }
    float* op = states + ((long long)(bh * NC + ck) * NST + n) * P_;
    #pragma unroll
    for (int p = 0; p < 64; p++) op[p] = acc[p];
}

// ---------------- inter-chunk scan ----------------
__global__ void scan_kernel(const float* __restrict__ states, const float* __restrict__ Acs,
                            float* __restrict__ Sprev)
{
    int bh = blockIdx.x;
    int tid = threadIdx.x;
    float S[32];
    #pragma unroll
    for (int j = 0; j < 32; j++) S[j] = 0.f;
    for (int c = 0; c < NC; c++) {
        float dc = __expf(Acs[(long long)bh * L_ + c * 256 + 255]);
        const float* sp = states + (long long)(bh * NC + c) * 8192;
        float* pp = Sprev + (long long)(bh * NC + c) * 8192;
        #pragma unroll
        for (int j = 0; j < 32; j++) {
            int idx = tid + j * 256;
            pp[idx] = S[j];
            S[j] = S[j] * dc + sp[idx];
        }
    }
}

// ---------------- Y: diag + off-diag + D*xs ----------------
__global__ void y_kernel(const float* __restrict__ xbc, const float* __restrict__ xdt,
                         const float* __restrict__ Acs, const float* __restrict__ CB,
                         const float* __restrict__ Sprev, const float* __restrict__ Dv,
                         float* __restrict__ Y)
{
    __shared__ float sh[128 * 64];
    __shared__ float acs_sh[256];
    int blk = blockIdx.x;
    int ck = blk & 7;
    int bh = blk >> 3;
    int h = bh & 31;
    int b = bh >> 5;
    int l = threadIdx.x;
    int gl = ck * 256 + l;
    long long row = (long long)(b * L_ + gl);

    acs_sh[l] = Acs[(long long)bh * L_ + gl];
    const float* spv = Sprev + (long long)(bh * NC + ck) * 8192;
    #pragma unroll
    for (int j = 0; j < 32; j++) sh[l + j * 256] = spv[l + j * 256];
    __syncthreads();

    float aL = acs_sh[l];
    float y[64];
    #pragma unroll
    for (int p = 0; p < 64; p++) y[p] = 0.f;

    {
        float eA = __expf(aL);
        const float* cp = xbc + row * CONVD + DI + NST;
        for (int n = 0; n < 128; n++) {
            float cn = cp[n] * eA;
            const float* sr = &sh[n * 64];
            #pragma unroll
            for (int p = 0; p < 64; p++) y[p] += cn * sr[p];
        }
    }

    const float* cbp = CB + (long long)(b * NC + ck) * (CH * CH);
    long long rowbase = (long long)(b * L_ + ck * 256);
    for (int st = 0; st < 4; st++) {
        __syncthreads();
        #pragma unroll
        for (int j = 0; j < 16; j++) {
            int idx = l + j * 256;
            int r = idx >> 6, p = idx & 63;
            sh[r * 64 + p] = xdt[(rowbase + st * 64 + r) * DI + h * 64 + p];
        }
        __syncthreads();
        for (int r = 0; r < 64; r++) {
            int s = st * 64 + r;
            if (s <= l) {
                float w = cbp[s * 256 + l] * __expf(aL - acs_sh[s]);
                const float* xr = &sh[r * 64];
                #pragma unroll
                for (int p = 0; p < 64; p++) y[p] += w * xr[p];
            }
        }
    }

    float Dh = Dv[h];
    const float* xsrow = xbc + row * CONVD + h * 64;
    float* op = Y + row * DI + h * 64;
    #pragma unroll
    for (int p = 0; p < 64; p++) op[p] = y[p] + Dh * xsrow[p];
}

// ---------------- swiglu ----------------
__global__ void swiglu_kernel(const float* __restrict__ y, float* __restrict__ ff)
{
    int idx = blockIdx.x * 256 + threadIdx.x;
    if (idx >= ROWS * DFF) return;
    long long row = idx / DFF;
    int f = idx % DFF;
    const float* yp = y + row * (2 * DFF);
    ff[idx] = yp[f] * silu_f(yp[f + DFF]);
}

// ---------------- host launcher ----------------
extern "C" void kernel_launch(void* const* d_in, const int* in_sizes, int n_in,
                              void* d_out, int out_size)
{
    const float* x_in       = (const float*)d_in[0];
    const float* attn_norm  = (const float*)d_in[1];
    const float* Wqkv       = (const float*)d_in[2];
    const float* Wqkv_b     = (const float*)d_in[3];
    const float* attn_out_w = (const float*)d_in[4];
    const float* attn_out_b = (const float*)d_in[5];
    const float* normf_w    = (const float*)d_in[6];
    const float* m_in_w     = (const float*)d_in[7];
    const float* m_conv_w   = (const float*)d_in[8];
    const float* m_conv_b   = (const float*)d_in[9];
    const float* m_dt_bias  = (const float*)d_in[10];
    const float* m_A_log    = (const float*)d_in[11];
    const float* m_D        = (const float*)d_in[12];
    const float* m_norm_w   = (const float*)d_in[13];
    const float* m_out_w    = (const float*)d_in[14];
    const float* fc1_w      = (const float*)d_in[15];
    const float* fc2_w      = (const float*)d_in[16];
    const float* final_norm = (const float*)d_in[17];
    float* out = (float*)d_out;

    float* scr = nullptr;
    cudaGetSymbolAddress((void**)&scr, g_scratch);

    float* bBIG = scr + OFF_BIG;
    float* bH   = scr + OFF_H;
    float* bO   = scr + OFF_O;
    float* bX   = scr + OFF_X;
    float* bXBC = scr + OFF_XBC;
    float* bDT  = scr + OFF_DT;
    float* bXDT = scr + OFF_XDT;
    float* bACS = scr + OFF_ACS;
    float* bCB  = scr + OFF_CB;
    float* bSTA = scr + OFF_STA;
    float* bSPR = scr + OFF_SPR;
    float* bY   = scr + OFF_Y;
    float* bFF  = scr + OFF_FF;

    // ---- attention block ----
    rmsnorm_kernel<<<ROWS, 256>>>(x_in, nullptr, 0.f, attn_norm, bH, DM);
    gemm_tc<<<dim3(3072/128, ROWS/128, 1), 256>>>(bH, Wqkv, Wqkv_b, bBIG,
        ROWS, 3072, DM, DM, DM, 3072, 0, 0, 0);
    attn_kernel<<<dim3(L_/64, B_*NH), 64>>>(bBIG, bO);
    gemm_tc<<<dim3(DM/128, ROWS/128, 1), 256>>>(bO, attn_out_w, attn_out_b, bH,
        ROWS, DM, DM, DM, DM, DM, 0, 0, 0);
    rmsnorm_kernel<<<ROWS, 256>>>(bH, x_in, 1.f, normf_w, bX, DM);

    // ---- mamba layers ----
    for (int i = 0; i < 4; i++) {
        const float* in_w   = m_in_w   + (long long)i * DINP * DM;
        const float* conv_w = m_conv_w + (long long)i * CONVD * 4;
        const float* conv_b = m_conv_b + (long long)i * CONVD;
        const float* dtbias = m_dt_bias+ (long long)i * HS;
        const float* Alog   = m_A_log  + (long long)i * HS;
        const float* Dv     = m_D      + (long long)i * HS;
        const float* nw     = m_norm_w + (long long)i * DI;
        const float* ow     = m_out_w  + (long long)i * DM * DI;

        gemm_tc<<<dim3((DINP+127)/128, ROWS/128, 1), 256>>>(bX, in_w, nullptr, bBIG,
            ROWS, DINP, DM, DM, DM, DINP, 0, 0, 0);
        conv_kernel<<<(ROWS*CONVD)/256, 256>>>(bBIG, conv_w, conv_b, bXBC);
        dtxdt_kernel<<<(ROWS*DI)/256, 256>>>(bBIG, bXBC, dtbias, bDT, bXDT);
        cumsum_kernel<<<B_*HS*NC, 256>>>(bDT, Alog, bACS);
        // CB[b,c][s][l] = Bm[s] . Cm[l]  (batched over b*c = 16)
        gemm_tc<<<dim3(2, 2, B_*NC), 256>>>(
            bXBC + DI, bXBC + DI + NST, nullptr, bCB,
            CH, CH, NST, CONVD, CONVD, CH,
            (long long)CH * CONVD, (long long)CH * CONVD, (long long)CH * CH);
        states_kernel<<<B_*HS*NC, 128>>>(bXBC, bXDT, bACS, bSTA);
        scan_kernel<<<B_*HS, 256>>>(bSTA, bACS, bSPR);
        y_kernel<<<B_*HS*NC, 256>>>(bXBC, bXDT, bACS, bCB, bSPR, Dv, bY);
        gated_rmsnorm_kernel<<<ROWS, 256>>>(bY, bBIG, DINP, nw, bY);
        gemm_tc<<<dim3(DM/128, ROWS/128, 1), 256>>>(bY, ow, nullptr, bX,
            ROWS, DM, DI, DI, DI, DM, 0, 0, 0);
    }

    // ---- MLP + final norm ----
    gemm_tc<<<dim3((2*DFF)/128, ROWS/128, 1), 256>>>(bX, fc1_w, nullptr, bBIG,
        ROWS, 2*DFF, DM, DM, DM, 2*DFF, 0, 0, 0);
    swiglu_kernel<<<(ROWS*DFF)/256, 256>>>(bBIG, bFF);
    gemm_tc<<<dim3(DM/128, ROWS/128, 1), 256>>>(bFF, fc2_w, nullptr, bH,
        ROWS, DM, DFF, DFF, DFF, DM, 0, 0, 0);
    rmsnorm_kernel<<<ROWS, 256>>>(bH, bX, ALPHA, final_norm, out, DM);
}

// round 5
// speedup vs baseline: 2.4584x; 1.1816x over previous
#include <cuda_runtime.h>
#include <cuda_bf16.h>
#include <math.h>
#include <stdint.h>

// ---------------- constants ----------------
#define B_   2
#define L_   2048
#define DM   1024          // D_MODEL
#define NH   16            // NHEAD
#define HD   64            // HD_ATT
#define DI   2048          // D_INNER
#define HS   32            // H_SSM
#define P_   64            // HEADDIM
#define NST  128           // D_STATE
#define CONVD 2304         // CONV_DIM
#define DINP 4384          // D_IN_PROJ
#define CH   256           // CHUNK
#define NC   8             // L/CHUNK
#define DFF  2048
#define ALPHA 1.68f
#define EPSN 1e-5f

#define ROWS (B_*L_)       // 4096

// ---------------- scratch ----------------
static const long long SZ_BIG  = (long long)ROWS*DINP;
static const long long SZ_HB   = (long long)ROWS*DM;
static const long long SZ_XBC  = (long long)ROWS*CONVD;
static const long long SZ_DT   = (long long)ROWS*HS;
static const long long SZ_XDT  = (long long)ROWS*DI;
static const long long SZ_ACS  = (long long)B_*HS*L_;
static const long long SZ_CB   = (long long)B_*NC*CH*CH;
static const long long SZ_ST   = (long long)B_*HS*NC*NST*P_;
static const long long SZ_Y    = (long long)ROWS*DI;

static const long long OFF_BIG = 0;
static const long long OFF_H   = OFF_BIG + SZ_BIG;
static const long long OFF_O   = OFF_H   + SZ_HB;
static const long long OFF_X   = OFF_O   + SZ_HB;
static const long long OFF_XBC = OFF_X   + SZ_HB;
static const long long OFF_DT  = OFF_XBC + SZ_XBC;
static const long long OFF_XDT = OFF_DT  + SZ_DT;
static const long long OFF_ACS = OFF_XDT + SZ_XDT;
static const long long OFF_CB  = OFF_ACS + SZ_ACS;
static const long long OFF_STA = OFF_CB  + SZ_CB;
static const long long OFF_SPR = OFF_STA + SZ_ST;
static const long long OFF_Y   = OFF_SPR + SZ_ST;
static const long long OFF_FF  = OFF_Y   + SZ_Y;
static const long long TOTALF  = OFF_FF  + SZ_Y;

__device__ float g_scratch[74842112]; // == TOTALF floats (~300 MB)

// ---------------- helpers ----------------
__device__ __forceinline__ float silu_f(float x) {
    return x / (1.f + __expf(-x));
}
__device__ __forceinline__ float softplus_f(float x) {
    return (x > 20.f) ? x : log1pf(__expf(x));
}
// split x into hi(bf16) + lo(bf16)
__device__ __forceinline__ void split_bf16(float x, __nv_bfloat16& hi, __nv_bfloat16& lo) {
    hi = __float2bfloat16_rn(x);
    lo = __float2bfloat16_rn(x - __bfloat162float(hi));
}
__device__ __forceinline__ uint32_t pack2(__nv_bfloat16 a, __nv_bfloat16 b) {
    __nv_bfloat162 h;
    h.x = a; h.y = b;
    return *(uint32_t*)&h;
}
__device__ __forceinline__ void mma_bf16(float* c, const uint32_t* a, const uint32_t* b) {
    asm volatile(
        "mma.sync.aligned.m16n8k16.row.col.f32.bf16.bf16.f32 "
        "{%0,%1,%2,%3}, {%4,%5,%6,%7}, {%8,%9}, {%0,%1,%2,%3};"
        : "+f"(c[0]), "+f"(c[1]), "+f"(c[2]), "+f"(c[3])
        : "r"(a[0]), "r"(a[1]), "r"(a[2]), "r"(a[3]), "r"(b[0]), "r"(b[1]));
}

// ---------------- bf16x2 split tensor-core NT GEMM, register-prefetch pipelined ----------------
// C[M,N] = A[M,K] @ W[N,K]^T (+bias), fp32 in/out, ~16-bit effective mantissa.
// CTA tile 128x128, K-tile 32, 256 threads = 8 warps (2x4), warp tile 64x32.
#define SSTR 20
__global__ __launch_bounds__(256, 2)
void gemm_tc(const float* __restrict__ A, const float* __restrict__ W,
             const float* __restrict__ bias, float* __restrict__ C,
             int M, int N, int K, int lda, int ldw, int ldc,
             long long sA, long long sW, long long sC)
{
    A += (long long)blockIdx.z * sA;
    W += (long long)blockIdx.z * sW;
    C += (long long)blockIdx.z * sC;

    __shared__ uint32_t Ahi[128][SSTR];
    __shared__ uint32_t Alo[128][SSTR];
    __shared__ uint32_t Bhi[128][SSTR];
    __shared__ uint32_t Blo[128][SSTR];

    int bm = blockIdx.y * 128, bn = blockIdx.x * 128;
    int tid = threadIdx.x;
    int wid = tid >> 5, lane = tid & 31;
    int wm = (wid >> 2) * 64;          // 0 or 64
    int wn = (wid & 3) * 32;           // 0,32,64,96
    int lr = lane >> 2;                // 0..7
    int lc = lane & 3;                 // 0..3

    int sr = tid >> 3;                 // row 0..31 within 32-row group
    int sc4 = (tid & 7) << 2;          // k-offset 0,4,...,28
    int sc2 = sc4 >> 1;                // packed-word offset

    float acc[4][4][4];
    #pragma unroll
    for (int i = 0; i < 4; i++)
        #pragma unroll
        for (int j = 0; j < 4; j++)
            #pragma unroll
            for (int r = 0; r < 4; r++) acc[i][j][r] = 0.f;

    float4 pa[4], pw[4];
    #pragma unroll
    for (int i = 0; i < 4; i++) {
        int r = sr + i * 32;
        pa[i] = *(const float4*)(A + (long long)(bm + r) * lda + sc4);
        if (bn + r < N) pw[i] = *(const float4*)(W + (long long)(bn + r) * ldw + sc4);
        else            pw[i] = make_float4(0.f, 0.f, 0.f, 0.f);
    }

    for (int k0 = 0; k0 < K; k0 += 32) {
        #pragma unroll
        for (int i = 0; i < 4; i++) {
            int r = sr + i * 32;
            __nv_bfloat16 h0,l0,h1,l1,h2,l2,h3,l3;
            split_bf16(pa[i].x, h0, l0); split_bf16(pa[i].y, h1, l1);
            split_bf16(pa[i].z, h2, l2); split_bf16(pa[i].w, h3, l3);
            Ahi[r][sc2]     = pack2(h0, h1);
            Ahi[r][sc2 + 1] = pack2(h2, h3);
            Alo[r][sc2]     = pack2(l0, l1);
            Alo[r][sc2 + 1] = pack2(l2, l3);
            split_bf16(pw[i].x, h0, l0); split_bf16(pw[i].y, h1, l1);
            split_bf16(pw[i].z, h2, l2); split_bf16(pw[i].w, h3, l3);
            Bhi[r][sc2]     = pack2(h0, h1);
            Bhi[r][sc2 + 1] = pack2(h2, h3);
            Blo[r][sc2]     = pack2(l0, l1);
            Blo[r][sc2 + 1] = pack2(l2, l3);
        }
        __syncthreads();

        if (k0 + 32 < K) {
            int kn = k0 + 32;
            #pragma unroll
            for (int i = 0; i < 4; i++) {
                int r = sr + i * 32;
                pa[i] = *(const float4*)(A + (long long)(bm + r) * lda + kn + sc4);
                if (bn + r < N) pw[i] = *(const float4*)(W + (long long)(bn + r) * ldw + kn + sc4);
                else            pw[i] = make_float4(0.f, 0.f, 0.f, 0.f);
            }
        }

        #pragma unroll
        for (int kk2 = 0; kk2 < 16; kk2 += 8) {
            uint32_t bh[4][2], bl[4][2];
            #pragma unroll
            for (int jn = 0; jn < 4; jn++) {
                int cdx = wn + jn * 8 + lr;
                bh[jn][0] = Bhi[cdx][kk2 + lc];
                bh[jn][1] = Bhi[cdx][kk2 + lc + 4];
                bl[jn][0] = Blo[cdx][kk2 + lc];
                bl[jn][1] = Blo[cdx][kk2 + lc + 4];
            }
            #pragma unroll
            for (int im = 0; im < 4; im++) {
                int r = wm + im * 16 + lr;
                uint32_t ah[4], al[4];
                ah[0] = Ahi[r][kk2 + lc];
                ah[1] = Ahi[r + 8][kk2 + lc];
                ah[2] = Ahi[r][kk2 + lc + 4];
                ah[3] = Ahi[r + 8][kk2 + lc + 4];
                al[0] = Alo[r][kk2 + lc];
                al[1] = Alo[r + 8][kk2 + lc];
                al[2] = Alo[r][kk2 + lc + 4];
                al[3] = Alo[r + 8][kk2 + lc + 4];
                #pragma unroll
                for (int jn = 0; jn < 4; jn++) {
                    mma_bf16(acc[im][jn], ah, bl[jn]);   // hi*lo
                    mma_bf16(acc[im][jn], al, bh[jn]);   // lo*hi
                    mma_bf16(acc[im][jn], ah, bh[jn]);   // hi*hi
                }
            }
        }
        __syncthreads();
    }

    #pragma unroll
    for (int im = 0; im < 4; im++) {
        #pragma unroll
        for (int jn = 0; jn < 4; jn++) {
            int gm = bm + wm + im * 16 + lr;
            int gc = bn + wn + jn * 8 + 2 * lc;
            if (gc < N) {
                float b0 = bias ? bias[gc] : 0.f;
                float b1 = bias ? bias[gc + 1] : 0.f;
                float* p0 = C + (long long)gm * ldc + gc;
                p0[0] = acc[im][jn][0] + b0;
                p0[1] = acc[im][jn][1] + b1;
                float* p1 = C + (long long)(gm + 8) * ldc + gc;
                p1[0] = acc[im][jn][2] + b0;
                p1[1] = acc[im][jn][3] + b1;
            }
        }
    }
}

// ---------------- tensor-core flash attention (non-causal), split-bf16 ----------------
// qkv row layout: [q(1024) | k(1024) | v(1024)], head h at offset h*64 in each.
// grid: (L/128, B*NH), 256 threads = 8 warps; warp w owns Q rows [blk*128 + w*16, +16).
__global__ __launch_bounds__(256)
void attn_tc_kernel(const float* __restrict__ qkv, float* __restrict__ o)
{
    __shared__ uint32_t Khi[64][36];            // [token n][packed k2 word]
    __shared__ uint32_t Klo[64][36];
    __shared__ __nv_bfloat16 Vthi[64][72];      // [d][token], padded
    __shared__ __nv_bfloat16 Vtlo[64][72];

    int bh = blockIdx.y;
    int b = bh >> 4, h = bh & 15;
    int tid = threadIdx.x;
    int wid = tid >> 5, lane = tid & 31;
    int lr = lane >> 2, lc = lane & 3;
    int qrow0 = blockIdx.x * 128 + wid * 16;

    // ---- load Q fragments (scaled by 1/sqrt(64)=0.125), resident in registers ----
    uint32_t qhi[4][4], qlo[4][4];
    {
        const float* qp = qkv + (long long)(b * L_) * 3072 + h * 64;
        #pragma unroll
        for (int kc = 0; kc < 4; kc++) {
            #pragma unroll
            for (int half = 0; half < 2; half++) {
                int col = kc * 16 + 2 * lc + half * 8;
                float2 v0 = *(const float2*)(qp + (long long)(qrow0 + lr) * 3072 + col);
                float2 v1 = *(const float2*)(qp + (long long)(qrow0 + lr + 8) * 3072 + col);
                __nv_bfloat16 h0,l0,h1,l1;
                split_bf16(v0.x * 0.125f, h0, l0); split_bf16(v0.y * 0.125f, h1, l1);
                qhi[kc][half * 2]     = pack2(h0, h1);
                qlo[kc][half * 2]     = pack2(l0, l1);
                split_bf16(v1.x * 0.125f, h0, l0); split_bf16(v1.y * 0.125f, h1, l1);
                qhi[kc][half * 2 + 1] = pack2(h0, h1);
                qlo[kc][half * 2 + 1] = pack2(l0, l1);
            }
        }
    }

    float o_acc[8][4];
    #pragma unroll
    for (int j = 0; j < 8; j++)
        #pragma unroll
        for (int r = 0; r < 4; r++) o_acc[j][r] = 0.f;
    float mrow0 = -1e30f, mrow1 = -1e30f;
    float lrow0 = 0.f, lrow1 = 0.f;

    for (int kt = 0; kt < L_ / 64; kt++) {
        // ---- stage K (packed k2) and V (transposed bf16) ----
        const float* kb = qkv + (long long)(b * L_ + kt * 64) * 3072 + 1024 + h * 64;
        const float* vb = kb + 1024;
        #pragma unroll
        for (int i = 0; i < 4; i++) {
            int idx = tid + i * 256;
            int r = idx >> 4, c4 = (idx & 15) << 2;
            float4 kv = *(const float4*)(kb + (long long)r * 3072 + c4);
            __nv_bfloat16 h0,l0,h1,l1,h2,l2,h3,l3;
            split_bf16(kv.x, h0, l0); split_bf16(kv.y, h1, l1);
            split_bf16(kv.z, h2, l2); split_bf16(kv.w, h3, l3);
            int c2 = c4 >> 1;
            Khi[r][c2]     = pack2(h0, h1);
            Khi[r][c2 + 1] = pack2(h2, h3);
            Klo[r][c2]     = pack2(l0, l1);
            Klo[r][c2 + 1] = pack2(l2, l3);
            float4 vv = *(const float4*)(vb + (long long)r * 3072 + c4);
            __nv_bfloat16 vh, vl;
            split_bf16(vv.x, vh, vl); Vthi[c4 + 0][r] = vh; Vtlo[c4 + 0][r] = vl;
            split_bf16(vv.y, vh, vl); Vthi[c4 + 1][r] = vh; Vtlo[c4 + 1][r] = vl;
            split_bf16(vv.z, vh, vl); Vthi[c4 + 2][r] = vh; Vtlo[c4 + 2][r] = vl;
            split_bf16(vv.w, vh, vl); Vthi[c4 + 3][r] = vh; Vtlo[c4 + 3][r] = vl;
        }
        __syncthreads();

        // ---- scores S = Q K^T (16 x 64 per warp) ----
        float s[8][4];
        #pragma unroll
        for (int j = 0; j < 8; j++)
            #pragma unroll
            for (int r = 0; r < 4; r++) s[j][r] = 0.f;
        #pragma unroll
        for (int kc = 0; kc < 4; kc++) {
            #pragma unroll
            for (int jn = 0; jn < 8; jn++) {
                int n = jn * 8 + lr;
                uint32_t bhf[2], blf[2];
                bhf[0] = Khi[n][kc * 8 + lc];
                bhf[1] = Khi[n][kc * 8 + lc + 4];
                blf[0] = Klo[n][kc * 8 + lc];
                blf[1] = Klo[n][kc * 8 + lc + 4];
                mma_bf16(s[jn], qhi[kc], blf);
                mma_bf16(s[jn], qlo[kc], bhf);
                mma_bf16(s[jn], qhi[kc], bhf);
            }
        }

        // ---- online softmax ----
        float t0 = -1e30f, t1 = -1e30f;
        #pragma unroll
        for (int jn = 0; jn < 8; jn++) {
            t0 = fmaxf(t0, fmaxf(s[jn][0], s[jn][1]));
            t1 = fmaxf(t1, fmaxf(s[jn][2], s[jn][3]));
        }
        t0 = fmaxf(t0, __shfl_xor_sync(0xffffffffu, t0, 1));
        t0 = fmaxf(t0, __shfl_xor_sync(0xffffffffu, t0, 2));
        t1 = fmaxf(t1, __shfl_xor_sync(0xffffffffu, t1, 1));
        t1 = fmaxf(t1, __shfl_xor_sync(0xffffffffu, t1, 2));
        float m0n = fmaxf(mrow0, t0), m1n = fmaxf(mrow1, t1);
        float sc0 = __expf(mrow0 - m0n), sc1 = __expf(mrow1 - m1n);
        mrow0 = m0n; mrow1 = m1n;
        lrow0 *= sc0; lrow1 *= sc1;
        #pragma unroll
        for (int j = 0; j < 8; j++) {
            o_acc[j][0] *= sc0; o_acc[j][1] *= sc0;
            o_acc[j][2] *= sc1; o_acc[j][3] *= sc1;
        }

        // ---- P = exp(S - m), pack into A fragments ----
        uint32_t phi[4][4], plo[4][4];
        #pragma unroll
        for (int jn = 0; jn < 8; jn++) {
            float p0 = __expf(s[jn][0] - m0n);
            float p1 = __expf(s[jn][1] - m0n);
            float p2 = __expf(s[jn][2] - m1n);
            float p3 = __expf(s[jn][3] - m1n);
            lrow0 += p0 + p1;
            lrow1 += p2 + p3;
            __nv_bfloat16 h0,l0,h1,l1,h2,l2,h3,l3;
            split_bf16(p0, h0, l0); split_bf16(p1, h1, l1);
            split_bf16(p2, h2, l2); split_bf16(p3, h3, l3);
            int kc = jn >> 1;
            int off = (jn & 1) * 2;
            phi[kc][off]     = pack2(h0, h1);
            phi[kc][off + 1] = pack2(h2, h3);
            plo[kc][off]     = pack2(l0, l1);
            plo[kc][off + 1] = pack2(l2, l3);
        }

        // ---- O += P V ----
        #pragma unroll
        for (int kc = 0; kc < 4; kc++) {
            #pragma unroll
            for (int jd = 0; jd < 8; jd++) {
                int d = jd * 8 + lr;
                uint32_t bhf[2], blf[2];
                bhf[0] = *(const uint32_t*)&Vthi[d][2 * (kc * 8 + lc)];
                bhf[1] = *(const uint32_t*)&Vthi[d][2 * (kc * 8 + lc + 4)];
                blf[0] = *(const uint32_t*)&Vtlo[d][2 * (kc * 8 + lc)];
                blf[1] = *(const uint32_t*)&Vtlo[d][2 * (kc * 8 + lc + 4)];
                mma_bf16(o_acc[jd], phi[kc], blf);
                mma_bf16(o_acc[jd], plo[kc], bhf);
                mma_bf16(o_acc[jd], phi[kc], bhf);
            }
        }
        __syncthreads();
    }

    // ---- finalize: reduce lsum over quad, normalize, store ----
    lrow0 += __shfl_xor_sync(0xffffffffu, lrow0, 1);
    lrow0 += __shfl_xor_sync(0xffffffffu, lrow0, 2);
    lrow1 += __shfl_xor_sync(0xffffffffu, lrow1, 1);
    lrow1 += __shfl_xor_sync(0xffffffffu, lrow1, 2);
    float inv0 = 1.f / lrow0, inv1 = 1.f / lrow1;
    #pragma unroll
    for (int jd = 0; jd < 8; jd++) {
        int col = h * 64 + jd * 8 + 2 * lc;
        float* p0 = o + (long long)(b * L_ + qrow0 + lr) * DM + col;
        p0[0] = o_acc[jd][0] * inv0;
        p0[1] = o_acc[jd][1] * inv0;
        float* p1 = o + (long long)(b * L_ + qrow0 + lr + 8) * DM + col;
        p1[0] = o_acc[jd][2] * inv1;
        p1[1] = o_acc[jd][3] * inv1;
    }
}

// ---------------- rmsnorm: out = rmsnorm(a + alpha*b, w) ----------------
__global__ void rmsnorm_kernel(const float* __restrict__ a, const float* __restrict__ b,
                               float alpha, const float* __restrict__ w,
                               float* __restrict__ out, int D)
{
    long long row = blockIdx.x;
    const float* ap = a + row * D;
    const float* bp = b ? (b + row * D) : nullptr;
    int per = D >> 8;
    float v[8];
    float ss = 0.f;
    for (int j = 0; j < per; j++) {
        int i = threadIdx.x + j * 256;
        float x = ap[i] + (bp ? alpha * bp[i] : 0.f);
        v[j] = x;
        ss += x * x;
    }
    __shared__ float red[256];
    red[threadIdx.x] = ss;
    __syncthreads();
    for (int off = 128; off; off >>= 1) {
        if (threadIdx.x < off) red[threadIdx.x] += red[threadIdx.x + off];
        __syncthreads();
    }
    float scale = rsqrtf(red[0] / D + EPSN);
    float* op = out + row * D;
    for (int j = 0; j < per; j++) {
        int i = threadIdx.x + j * 256;
        op[i] = v[j] * scale * w[i];
    }
}

// ---------------- gated rmsnorm ----------------
__global__ void gated_rmsnorm_kernel(const float* __restrict__ y, const float* __restrict__ z,
                                     int ldz, const float* __restrict__ w,
                                     float* __restrict__ out)
{
    long long row = blockIdx.x;
    const float* yp = y + row * DI;
    const float* zp = z + row * (long long)ldz;
    float v[8];
    float ss = 0.f;
    #pragma unroll
    for (int j = 0; j < 8; j++) {
        int i = threadIdx.x + j * 256;
        float x = yp[i] * silu_f(zp[i]);
        v[j] = x;
        ss += x * x;
    }
    __shared__ float red[256];
    red[threadIdx.x] = ss;
    __syncthreads();
    for (int off = 128; off; off >>= 1) {
        if (threadIdx.x < off) red[threadIdx.x] += red[threadIdx.x + off];
        __syncthreads();
    }
    float scale = rsqrtf(red[0] / DI + EPSN);
    float* op = out + row * DI;
    #pragma unroll
    for (int j = 0; j < 8; j++) {
        int i = threadIdx.x + j * 256;
        op[i] = v[j] * scale * w[i];
    }
}

// ---------------- depthwise causal conv (k=4) + bias + silu ----------------
__global__ void conv_kernel(const float* __restrict__ zx, const float* __restrict__ cw,
                            const float* __restrict__ cb, float* __restrict__ xbc)
{
    int idx = blockIdx.x * 256 + threadIdx.x;
    if (idx >= B_ * L_ * CONVD) return;
    int c = idx % CONVD;
    int t = (idx / CONVD) % L_;
    int b = idx / (CONVD * L_);
    float s = cb[c];
    #pragma unroll
    for (int k = 0; k < 4; k++) {
        int tt = t - 3 + k;
        if (tt >= 0)
            s += zx[((long long)(b * L_ + tt) * DINP) + DI + c] * cw[c * 4 + k];
    }
    xbc[idx] = silu_f(s);
}

// ---------------- dt (softplus) and xdt = xs*dt ----------------
__global__ void dtxdt_kernel(const float* __restrict__ zx, const float* __restrict__ xbc,
                             const float* __restrict__ dt_bias,
                             float* __restrict__ dtb, float* __restrict__ xdt)
{
    int idx = blockIdx.x * 256 + threadIdx.x;
    if (idx >= ROWS * DI) return;
    int p = idx & 63;
    int h = (idx >> 6) & 31;
    long long row = idx >> 11;
    float raw = zx[row * DINP + DI + CONVD + h] + dt_bias[h];
    float d = softplus_f(raw);
    xdt[idx] = xbc[row * CONVD + h * 64 + p] * d;
    if (p == 0) dtb[row * HS + h] = d;
}

// ---------------- per-chunk inclusive cumsum ----------------
__global__ void cumsum_kernel(const float* __restrict__ dtb, const float* __restrict__ A_log,
                              float* __restrict__ Acs)
{
    __shared__ float s[256];
    int blk = blockIdx.x;
    int ck = blk & 7;
    int bh = blk >> 3;
    int h = bh & 31;
    int b = bh >> 5;
    int l = threadIdx.x;
    int gl = ck * 256 + l;
    float a = -__expf(A_log[h]) * dtb[((long long)(b * L_ + gl)) * HS + h];
    s[l] = a;
    __syncthreads();
    for (int off = 1; off < 256; off <<= 1) {
        float t = (l >= off) ? s[l - off] : 0.f;
        __syncthreads();
        s[l] += t;
        __syncthreads();
    }
    Acs[(long long)bh * L_ + gl] = s[l];
}

// ---------------- chunk states ----------------
__global__ void states_kernel(const float* __restrict__ xbc, const float* __restrict__ xdt,
                              const float* __restrict__ Acs, float* __restrict__ states)
{
    __shared__ float xs_sh[8][64];
    __shared__ float dec[256];
    int blk = blockIdx.x;
    int ck = blk & 7;
    int bh = blk >> 3;
    int h = bh & 31;
    int b = bh >> 5;
    int n = threadIdx.x;
    const float* acs = Acs + (long long)bh * L_ + ck * 256;
    float aLast = acs[255];
    for (int i = n; i < 256; i += 128) dec[i] = __expf(aLast - acs[i]);
    float acc[64];
    #pragma unroll
    for (int p = 0; p < 64; p++) acc[p] = 0.f;
    long long rowbase = (long long)(b * L_ + ck * 256);
    for (int lt = 0; lt < 32; lt++) {
        __syncthreads();
        #pragma unroll
        for (int i = 0; i < 4; i++) {
            int idx = n + i * 128;
            int r = idx >> 6, p = idx & 63;
            xs_sh[r][p] = xdt[(rowbase + lt * 8 + r) * DI + h * 64 + p];
        }
        __syncthreads();
        #pragma unroll
        for (int r = 0; r < 8; r++) {
            int l = lt * 8 + r;
            float w = xbc[(rowbase + l) * CONVD + DI + n] * dec[l];
            #pragma unroll
            for (int p = 0; p < 64; p++) acc[p] += w * xs_sh[r][p];
        }
    }
    float* op = states + ((long long)(bh * NC + ck) * NST + n) * P_;
    #pragma unroll
    for (int p = 0; p < 64; p++) op[p] = acc[p];
}

// ---------------- inter-chunk scan ----------------
__global__ void scan_kernel(const float* __restrict__ states, const float* __restrict__ Acs,
                            float* __restrict__ Sprev)
{
    int bh = blockIdx.x;
    int tid = threadIdx.x;
    float S[32];
    #pragma unroll
    for (int j = 0; j < 32; j++) S[j] = 0.f;
    for (int c = 0; c < NC; c++) {
        float dc = __expf(Acs[(long long)bh * L_ + c * 256 + 255]);
        const float* sp = states + (long long)(bh * NC + c) * 8192;
        float* pp = Sprev + (long long)(bh * NC + c) * 8192;
        #pragma unroll
        for (int j = 0; j < 32; j++) {
            int idx = tid + j * 256;
            pp[idx] = S[j];
            S[j] = S[j] * dc + sp[idx];
        }
    }
}

// ---------------- Y: diag + off-diag + D*xs ----------------
__global__ void y_kernel(const float* __restrict__ xbc, const float* __restrict__ xdt,
                         const float* __restrict__ Acs, const float* __restrict__ CB,
                         const float* __restrict__ Sprev, const float* __restrict__ Dv,
                         float* __restrict__ Y)
{
    __shared__ float sh[128 * 64];
    __shared__ float acs_sh[256];
    int blk = blockIdx.x;
    int ck = blk & 7;
    int bh = blk >> 3;
    int h = bh & 31;
    int b = bh >> 5;
    int l = threadIdx.x;
    int gl = ck * 256 + l;
    long long row = (long long)(b * L_ + gl);

    acs_sh[l] = Acs[(long long)bh * L_ + gl];
    const float* spv = Sprev + (long long)(bh * NC + ck) * 8192;
    #pragma unroll
    for (int j = 0; j < 32; j++) sh[l + j * 256] = spv[l + j * 256];
    __syncthreads();

    float aL = acs_sh[l];
    float y[64];
    #pragma unroll
    for (int p = 0; p < 64; p++) y[p] = 0.f;

    {
        float eA = __expf(aL);
        const float* cp = xbc + row * CONVD + DI + NST;
        for (int n = 0; n < 128; n++) {
            float cn = cp[n] * eA;
            const float* sr = &sh[n * 64];
            #pragma unroll
            for (int p = 0; p < 64; p++) y[p] += cn * sr[p];
        }
    }

    const float* cbp = CB + (long long)(b * NC + ck) * (CH * CH);
    long long rowbase = (long long)(b * L_ + ck * 256);
    for (int st = 0; st < 4; st++) {
        __syncthreads();
        #pragma unroll
        for (int j = 0; j < 16; j++) {
            int idx = l + j * 256;
            int r = idx >> 6, p = idx & 63;
            sh[r * 64 + p] = xdt[(rowbase + st * 64 + r) * DI + h * 64 + p];
        }
        __syncthreads();
        for (int r = 0; r < 64; r++) {
            int s = st * 64 + r;
            if (s <= l) {
                float w = cbp[s * 256 + l] * __expf(aL - acs_sh[s]);
                const float* xr = &sh[r * 64];
                #pragma unroll
                for (int p = 0; p < 64; p++) y[p] += w * xr[p];
            }
        }
    }

    float Dh = Dv[h];
    const float* xsrow = xbc + row * CONVD + h * 64;
    float* op = Y + row * DI + h * 64;
    #pragma unroll
    for (int p = 0; p < 64; p++) op[p] = y[p] + Dh * xsrow[p];
}

// ---------------- swiglu ----------------
__global__ void swiglu_kernel(const float* __restrict__ y, float* __restrict__ ff)
{
    int idx = blockIdx.x * 256 + threadIdx.x;
    if (idx >= ROWS * DFF) return;
    long long row = idx / DFF;
    int f = idx % DFF;
    const float* yp = y + row * (2 * DFF);
    ff[idx] = yp[f] * silu_f(yp[f + DFF]);
}

// ---------------- host launcher ----------------
extern "C" void kernel_launch(void* const* d_in, const int* in_sizes, int n_in,
                              void* d_out, int out_size)
{
    const float* x_in       = (const float*)d_in[0];
    const float* attn_norm  = (const float*)d_in[1];
    const float* Wqkv       = (const float*)d_in[2];
    const float* Wqkv_b     = (const float*)d_in[3];
    const float* attn_out_w = (const float*)d_in[4];
    const float* attn_out_b = (const float*)d_in[5];
    const float* normf_w    = (const float*)d_in[6];
    const float* m_in_w     = (const float*)d_in[7];
    const float* m_conv_w   = (const float*)d_in[8];
    const float* m_conv_b   = (const float*)d_in[9];
    const float* m_dt_bias  = (const float*)d_in[10];
    const float* m_A_log    = (const float*)d_in[11];
    const float* m_D        = (const float*)d_in[12];
    const float* m_norm_w   = (const float*)d_in[13];
    const float* m_out_w    = (const float*)d_in[14];
    const float* fc1_w      = (const float*)d_in[15];
    const float* fc2_w      = (const float*)d_in[16];
    const float* final_norm = (const float*)d_in[17];
    float* out = (float*)d_out;

    float* scr = nullptr;
    cudaGetSymbolAddress((void**)&scr, g_scratch);

    float* bBIG = scr + OFF_BIG;
    float* bH   = scr + OFF_H;
    float* bO   = scr + OFF_O;
    float* bX   = scr + OFF_X;
    float* bXBC = scr + OFF_XBC;
    float* bDT  = scr + OFF_DT;
    float* bXDT = scr + OFF_XDT;
    float* bACS = scr + OFF_ACS;
    float* bCB  = scr + OFF_CB;
    float* bSTA = scr + OFF_STA;
    float* bSPR = scr + OFF_SPR;
    float* bY   = scr + OFF_Y;
    float* bFF  = scr + OFF_FF;

    // ---- attention block ----
    rmsnorm_kernel<<<ROWS, 256>>>(x_in, nullptr, 0.f, attn_norm, bH, DM);
    gemm_tc<<<dim3(3072/128, ROWS/128, 1), 256>>>(bH, Wqkv, Wqkv_b, bBIG,
        ROWS, 3072, DM, DM, DM, 3072, 0, 0, 0);
    attn_tc_kernel<<<dim3(L_/128, B_*NH), 256>>>(bBIG, bO);
    gemm_tc<<<dim3(DM/128, ROWS/128, 1), 256>>>(bO, attn_out_w, attn_out_b, bH,
        ROWS, DM, DM, DM, DM, DM, 0, 0, 0);
    rmsnorm_kernel<<<ROWS, 256>>>(bH, x_in, 1.f, normf_w, bX, DM);

    // ---- mamba layers ----
    for (int i = 0; i < 4; i++) {
        const float* in_w   = m_in_w   + (long long)i * DINP * DM;
        const float* conv_w = m_conv_w + (long long)i * CONVD * 4;
        const float* conv_b = m_conv_b + (long long)i * CONVD;
        const float* dtbias = m_dt_bias+ (long long)i * HS;
        const float* Alog   = m_A_log  + (long long)i * HS;
        const float* Dv     = m_D      + (long long)i * HS;
        const float* nw     = m_norm_w + (long long)i * DI;
        const float* ow     = m_out_w  + (long long)i * DM * DI;

        gemm_tc<<<dim3((DINP+127)/128, ROWS/128, 1), 256>>>(bX, in_w, nullptr, bBIG,
            ROWS, DINP, DM, DM, DM, DINP, 0, 0, 0);
        conv_kernel<<<(ROWS*CONVD)/256, 256>>>(bBIG, conv_w, conv_b, bXBC);
        dtxdt_kernel<<<(ROWS*DI)/256, 256>>>(bBIG, bXBC, dtbias, bDT, bXDT);
        cumsum_kernel<<<B_*HS*NC, 256>>>(bDT, Alog, bACS);
        // CB[b,c][s][l] = Bm[s] . Cm[l]  (batched over b*c = 16)
        gemm_tc<<<dim3(2, 2, B_*NC), 256>>>(
            bXBC + DI, bXBC + DI + NST, nullptr, bCB,
            CH, CH, NST, CONVD, CONVD, CH,
            (long long)CH * CONVD, (long long)CH * CONVD, (long long)CH * CH);
        states_kernel<<<B_*HS*NC, 128>>>(bXBC, bXDT, bACS, bSTA);
        scan_kernel<<<B_*HS, 256>>>(bSTA, bACS, bSPR);
        y_kernel<<<B_*HS*NC, 256>>>(bXBC, bXDT, bACS, bCB, bSPR, Dv, bY);
        gated_rmsnorm_kernel<<<ROWS, 256>>>(bY, bBIG, DINP, nw, bY);
        gemm_tc<<<dim3(DM/128, ROWS/128, 1), 256>>>(bY, ow, nullptr, bX,
            ROWS, DM, DI, DI, DI, DM, 0, 0, 0);
    }

    // ---- MLP + final norm ----
    gemm_tc<<<dim3((2*DFF)/128, ROWS/128, 1), 256>>>(bX, fc1_w, nullptr, bBIG,
        ROWS, 2*DFF, DM, DM, DM, 2*DFF, 0, 0, 0);
    swiglu_kernel<<<(ROWS*DFF)/256, 256>>>(bBIG, bFF);
    gemm_tc<<<dim3(DM/128, ROWS/128, 1), 256>>>(bFF, fc2_w, nullptr, bH,
        ROWS, DM, DFF, DFF, DFF, DM, 0, 0, 0);
    rmsnorm_kernel<<<ROWS, 256>>>(bH, bX, ALPHA, final_norm, out, DM);
}

// round 6
// speedup vs baseline: 2.9421x; 1.1968x over previous
#include <cuda_runtime.h>
#include <cuda_bf16.h>
#include <math.h>
#include <stdint.h>

// ---------------- constants ----------------
#define B_   2
#define L_   2048
#define DM   1024          // D_MODEL
#define NH   16            // NHEAD
#define HD   64            // HD_ATT
#define DI   2048          // D_INNER
#define HS   32            // H_SSM
#define P_   64            // HEADDIM
#define NST  128           // D_STATE
#define CONVD 2304         // CONV_DIM
#define DINP 4384          // D_IN_PROJ
#define CH   256           // CHUNK
#define NC   8             // L/CHUNK
#define DFF  2048
#define ALPHA 1.68f
#define EPSN 1e-5f

#define ROWS (B_*L_)       // 4096

// ---------------- scratch ----------------
static const long long SZ_BIG  = (long long)ROWS*DINP;
static const long long SZ_HB   = (long long)ROWS*DM;
static const long long SZ_XBC  = (long long)ROWS*CONVD;
static const long long SZ_DT   = (long long)ROWS*HS;
static const long long SZ_XDT  = (long long)ROWS*DI;
static const long long SZ_ACS  = (long long)B_*HS*L_;
static const long long SZ_CB   = (long long)B_*NC*CH*CH;
static const long long SZ_ST   = (long long)B_*HS*NC*NST*P_;
static const long long SZ_Y    = (long long)ROWS*DI;

static const long long OFF_BIG = 0;
static const long long OFF_H   = OFF_BIG + SZ_BIG;
static const long long OFF_O   = OFF_H   + SZ_HB;
static const long long OFF_X   = OFF_O   + SZ_HB;
static const long long OFF_XBC = OFF_X   + SZ_HB;
static const long long OFF_DT  = OFF_XBC + SZ_XBC;
static const long long OFF_XDT = OFF_DT  + SZ_DT;
static const long long OFF_ACS = OFF_XDT + SZ_XDT;
static const long long OFF_CB  = OFF_ACS + SZ_ACS;
static const long long OFF_STA = OFF_CB  + SZ_CB;
static const long long OFF_SPR = OFF_STA + SZ_ST;
static const long long OFF_Y   = OFF_SPR + SZ_ST;
static const long long OFF_FF  = OFF_Y   + SZ_Y;
static const long long TOTALF  = OFF_FF  + SZ_Y;

__device__ float g_scratch[74842112]; // == TOTALF floats (~300 MB)

// ---------------- helpers ----------------
__device__ __forceinline__ float silu_f(float x) {
    return x / (1.f + __expf(-x));
}
__device__ __forceinline__ float softplus_f(float x) {
    return (x > 20.f) ? x : log1pf(__expf(x));
}
__device__ __forceinline__ void split_bf16(float x, __nv_bfloat16& hi, __nv_bfloat16& lo) {
    hi = __float2bfloat16_rn(x);
    lo = __float2bfloat16_rn(x - __bfloat162float(hi));
}
__device__ __forceinline__ uint32_t pack2(__nv_bfloat16 a, __nv_bfloat16 b) {
    __nv_bfloat162 h;
    h.x = a; h.y = b;
    return *(uint32_t*)&h;
}
__device__ __forceinline__ void mma_bf16(float* c, const uint32_t* a, const uint32_t* b) {
    asm volatile(
        "mma.sync.aligned.m16n8k16.row.col.f32.bf16.bf16.f32 "
        "{%0,%1,%2,%3}, {%4,%5,%6,%7}, {%8,%9}, {%0,%1,%2,%3};"
        : "+f"(c[0]), "+f"(c[1]), "+f"(c[2]), "+f"(c[3])
        : "r"(a[0]), "r"(a[1]), "r"(a[2]), "r"(a[3]), "r"(b[0]), "r"(b[1]));
}

// ---------------- bf16x2 split tensor-core NT GEMM, register-prefetch pipelined ----------------
#define SSTR 20
__global__ __launch_bounds__(256, 2)
void gemm_tc(const float* __restrict__ A, const float* __restrict__ W,
             const float* __restrict__ bias, float* __restrict__ C,
             int M, int N, int K, int lda, int ldw, int ldc,
             long long sA, long long sW, long long sC)
{
    A += (long long)blockIdx.z * sA;
    W += (long long)blockIdx.z * sW;
    C += (long long)blockIdx.z * sC;

    __shared__ uint32_t Ahi[128][SSTR];
    __shared__ uint32_t Alo[128][SSTR];
    __shared__ uint32_t Bhi[128][SSTR];
    __shared__ uint32_t Blo[128][SSTR];

    int bm = blockIdx.y * 128, bn = blockIdx.x * 128;
    int tid = threadIdx.x;
    int wid = tid >> 5, lane = tid & 31;
    int wm = (wid >> 2) * 64;
    int wn = (wid & 3) * 32;
    int lr = lane >> 2;
    int lc = lane & 3;

    int sr = tid >> 3;
    int sc4 = (tid & 7) << 2;
    int sc2 = sc4 >> 1;

    float acc[4][4][4];
    #pragma unroll
    for (int i = 0; i < 4; i++)
        #pragma unroll
        for (int j = 0; j < 4; j++)
            #pragma unroll
            for (int r = 0; r < 4; r++) acc[i][j][r] = 0.f;

    float4 pa[4], pw[4];
    #pragma unroll
    for (int i = 0; i < 4; i++) {
        int r = sr + i * 32;
        pa[i] = *(const float4*)(A + (long long)(bm + r) * lda + sc4);
        if (bn + r < N) pw[i] = *(const float4*)(W + (long long)(bn + r) * ldw + sc4);
        else            pw[i] = make_float4(0.f, 0.f, 0.f, 0.f);
    }

    for (int k0 = 0; k0 < K; k0 += 32) {
        #pragma unroll
        for (int i = 0; i < 4; i++) {
            int r = sr + i * 32;
            __nv_bfloat16 h0,l0,h1,l1,h2,l2,h3,l3;
            split_bf16(pa[i].x, h0, l0); split_bf16(pa[i].y, h1, l1);
            split_bf16(pa[i].z, h2, l2); split_bf16(pa[i].w, h3, l3);
            Ahi[r][sc2]     = pack2(h0, h1);
            Ahi[r][sc2 + 1] = pack2(h2, h3);
            Alo[r][sc2]     = pack2(l0, l1);
            Alo[r][sc2 + 1] = pack2(l2, l3);
            split_bf16(pw[i].x, h0, l0); split_bf16(pw[i].y, h1, l1);
            split_bf16(pw[i].z, h2, l2); split_bf16(pw[i].w, h3, l3);
            Bhi[r][sc2]     = pack2(h0, h1);
            Bhi[r][sc2 + 1] = pack2(h2, h3);
            Blo[r][sc2]     = pack2(l0, l1);
            Blo[r][sc2 + 1] = pack2(l2, l3);
        }
        __syncthreads();

        if (k0 + 32 < K) {
            int kn = k0 + 32;
            #pragma unroll
            for (int i = 0; i < 4; i++) {
                int r = sr + i * 32;
                pa[i] = *(const float4*)(A + (long long)(bm + r) * lda + kn + sc4);
                if (bn + r < N) pw[i] = *(const float4*)(W + (long long)(bn + r) * ldw + kn + sc4);
                else            pw[i] = make_float4(0.f, 0.f, 0.f, 0.f);
            }
        }

        #pragma unroll
        for (int kk2 = 0; kk2 < 16; kk2 += 8) {
            uint32_t bh[4][2], bl[4][2];
            #pragma unroll
            for (int jn = 0; jn < 4; jn++) {
                int cdx = wn + jn * 8 + lr;
                bh[jn][0] = Bhi[cdx][kk2 + lc];
                bh[jn][1] = Bhi[cdx][kk2 + lc + 4];
                bl[jn][0] = Blo[cdx][kk2 + lc];
                bl[jn][1] = Blo[cdx][kk2 + lc + 4];
            }
            #pragma unroll
            for (int im = 0; im < 4; im++) {
                int r = wm + im * 16 + lr;
                uint32_t ah[4], al[4];
                ah[0] = Ahi[r][kk2 + lc];
                ah[1] = Ahi[r + 8][kk2 + lc];
                ah[2] = Ahi[r][kk2 + lc + 4];
                ah[3] = Ahi[r + 8][kk2 + lc + 4];
                al[0] = Alo[r][kk2 + lc];
                al[1] = Alo[r + 8][kk2 + lc];
                al[2] = Alo[r][kk2 + lc + 4];
                al[3] = Alo[r + 8][kk2 + lc + 4];
                #pragma unroll
                for (int jn = 0; jn < 4; jn++) {
                    mma_bf16(acc[im][jn], ah, bl[jn]);
                    mma_bf16(acc[im][jn], al, bh[jn]);
                    mma_bf16(acc[im][jn], ah, bh[jn]);
                }
            }
        }
        __syncthreads();
    }

    #pragma unroll
    for (int im = 0; im < 4; im++) {
        #pragma unroll
        for (int jn = 0; jn < 4; jn++) {
            int gm = bm + wm + im * 16 + lr;
            int gc = bn + wn + jn * 8 + 2 * lc;
            if (gc < N) {
                float b0 = bias ? bias[gc] : 0.f;
                float b1 = bias ? bias[gc + 1] : 0.f;
                float* p0 = C + (long long)gm * ldc + gc;
                p0[0] = acc[im][jn][0] + b0;
                p0[1] = acc[im][jn][1] + b1;
                float* p1 = C + (long long)(gm + 8) * ldc + gc;
                p1[0] = acc[im][jn][2] + b0;
                p1[1] = acc[im][jn][3] + b1;
            }
        }
    }
}

// ---------------- tensor-core flash attention (non-causal), split-bf16 ----------------
__global__ __launch_bounds__(256)
void attn_tc_kernel(const float* __restrict__ qkv, float* __restrict__ o)
{
    __shared__ uint32_t Khi[64][36];
    __shared__ uint32_t Klo[64][36];
    __shared__ __nv_bfloat16 Vthi[64][72];
    __shared__ __nv_bfloat16 Vtlo[64][72];

    int bh = blockIdx.y;
    int b = bh >> 4, h = bh & 15;
    int tid = threadIdx.x;
    int wid = tid >> 5, lane = tid & 31;
    int lr = lane >> 2, lc = lane & 3;
    int qrow0 = blockIdx.x * 128 + wid * 16;

    uint32_t qhi[4][4], qlo[4][4];
    {
        const float* qp = qkv + (long long)(b * L_) * 3072 + h * 64;
        #pragma unroll
        for (int kc = 0; kc < 4; kc++) {
            #pragma unroll
            for (int half = 0; half < 2; half++) {
                int col = kc * 16 + 2 * lc + half * 8;
                float2 v0 = *(const float2*)(qp + (long long)(qrow0 + lr) * 3072 + col);
                float2 v1 = *(const float2*)(qp + (long long)(qrow0 + lr + 8) * 3072 + col);
                __nv_bfloat16 h0,l0,h1,l1;
                split_bf16(v0.x * 0.125f, h0, l0); split_bf16(v0.y * 0.125f, h1, l1);
                qhi[kc][half * 2]     = pack2(h0, h1);
                qlo[kc][half * 2]     = pack2(l0, l1);
                split_bf16(v1.x * 0.125f, h0, l0); split_bf16(v1.y * 0.125f, h1, l1);
                qhi[kc][half * 2 + 1] = pack2(h0, h1);
                qlo[kc][half * 2 + 1] = pack2(l0, l1);
            }
        }
    }

    float o_acc[8][4];
    #pragma unroll
    for (int j = 0; j < 8; j++)
        #pragma unroll
        for (int r = 0; r < 4; r++) o_acc[j][r] = 0.f;
    float mrow0 = -1e30f, mrow1 = -1e30f;
    float lrow0 = 0.f, lrow1 = 0.f;

    for (int kt = 0; kt < L_ / 64; kt++) {
        const float* kb = qkv + (long long)(b * L_ + kt * 64) * 3072 + 1024 + h * 64;
        const float* vb = kb + 1024;
        #pragma unroll
        for (int i = 0; i < 4; i++) {
            int idx = tid + i * 256;
            int r = idx >> 4, c4 = (idx & 15) << 2;
            float4 kv = *(const float4*)(kb + (long long)r * 3072 + c4);
            __nv_bfloat16 h0,l0,h1,l1,h2,l2,h3,l3;
            split_bf16(kv.x, h0, l0); split_bf16(kv.y, h1, l1);
            split_bf16(kv.z, h2, l2); split_bf16(kv.w, h3, l3);
            int c2 = c4 >> 1;
            Khi[r][c2]     = pack2(h0, h1);
            Khi[r][c2 + 1] = pack2(h2, h3);
            Klo[r][c2]     = pack2(l0, l1);
            Klo[r][c2 + 1] = pack2(l2, l3);
            float4 vv = *(const float4*)(vb + (long long)r * 3072 + c4);
            __nv_bfloat16 vh, vl;
            split_bf16(vv.x, vh, vl); Vthi[c4 + 0][r] = vh; Vtlo[c4 + 0][r] = vl;
            split_bf16(vv.y, vh, vl); Vthi[c4 + 1][r] = vh; Vtlo[c4 + 1][r] = vl;
            split_bf16(vv.z, vh, vl); Vthi[c4 + 2][r] = vh; Vtlo[c4 + 2][r] = vl;
            split_bf16(vv.w, vh, vl); Vthi[c4 + 3][r] = vh; Vtlo[c4 + 3][r] = vl;
        }
        __syncthreads();

        float s[8][4];
        #pragma unroll
        for (int j = 0; j < 8; j++)
            #pragma unroll
            for (int r = 0; r < 4; r++) s[j][r] = 0.f;
        #pragma unroll
        for (int kc = 0; kc < 4; kc++) {
            #pragma unroll
            for (int jn = 0; jn < 8; jn++) {
                int n = jn * 8 + lr;
                uint32_t bhf[2], blf[2];
                bhf[0] = Khi[n][kc * 8 + lc];
                bhf[1] = Khi[n][kc * 8 + lc + 4];
                blf[0] = Klo[n][kc * 8 + lc];
                blf[1] = Klo[n][kc * 8 + lc + 4];
                mma_bf16(s[jn], qhi[kc], blf);
                mma_bf16(s[jn], qlo[kc], bhf);
                mma_bf16(s[jn], qhi[kc], bhf);
            }
        }

        float t0 = -1e30f, t1 = -1e30f;
        #pragma unroll
        for (int jn = 0; jn < 8; jn++) {
            t0 = fmaxf(t0, fmaxf(s[jn][0], s[jn][1]));
            t1 = fmaxf(t1, fmaxf(s[jn][2], s[jn][3]));
        }
        t0 = fmaxf(t0, __shfl_xor_sync(0xffffffffu, t0, 1));
        t0 = fmaxf(t0, __shfl_xor_sync(0xffffffffu, t0, 2));
        t1 = fmaxf(t1, __shfl_xor_sync(0xffffffffu, t1, 1));
        t1 = fmaxf(t1, __shfl_xor_sync(0xffffffffu, t1, 2));
        float m0n = fmaxf(mrow0, t0), m1n = fmaxf(mrow1, t1);
        float sc0 = __expf(mrow0 - m0n), sc1 = __expf(mrow1 - m1n);
        mrow0 = m0n; mrow1 = m1n;
        lrow0 *= sc0; lrow1 *= sc1;
        #pragma unroll
        for (int j = 0; j < 8; j++) {
            o_acc[j][0] *= sc0; o_acc[j][1] *= sc0;
            o_acc[j][2] *= sc1; o_acc[j][3] *= sc1;
        }

        uint32_t phi[4][4], plo[4][4];
        #pragma unroll
        for (int jn = 0; jn < 8; jn++) {
            float p0 = __expf(s[jn][0] - m0n);
            float p1 = __expf(s[jn][1] - m0n);
            float p2 = __expf(s[jn][2] - m1n);
            float p3 = __expf(s[jn][3] - m1n);
            lrow0 += p0 + p1;
            lrow1 += p2 + p3;
            __nv_bfloat16 h0,l0,h1,l1,h2,l2,h3,l3;
            split_bf16(p0, h0, l0); split_bf16(p1, h1, l1);
            split_bf16(p2, h2, l2); split_bf16(p3, h3, l3);
            int kc = jn >> 1;
            int off = (jn & 1) * 2;
            phi[kc][off]     = pack2(h0, h1);
            phi[kc][off + 1] = pack2(h2, h3);
            plo[kc][off]     = pack2(l0, l1);
            plo[kc][off + 1] = pack2(l2, l3);
        }

        #pragma unroll
        for (int kc = 0; kc < 4; kc++) {
            #pragma unroll
            for (int jd = 0; jd < 8; jd++) {
                int d = jd * 8 + lr;
                uint32_t bhf[2], blf[2];
                bhf[0] = *(const uint32_t*)&Vthi[d][2 * (kc * 8 + lc)];
                bhf[1] = *(const uint32_t*)&Vthi[d][2 * (kc * 8 + lc + 4)];
                blf[0] = *(const uint32_t*)&Vtlo[d][2 * (kc * 8 + lc)];
                blf[1] = *(const uint32_t*)&Vtlo[d][2 * (kc * 8 + lc + 4)];
                mma_bf16(o_acc[jd], phi[kc], blf);
                mma_bf16(o_acc[jd], plo[kc], bhf);
                mma_bf16(o_acc[jd], phi[kc], bhf);
            }
        }
        __syncthreads();
    }

    lrow0 += __shfl_xor_sync(0xffffffffu, lrow0, 1);
    lrow0 += __shfl_xor_sync(0xffffffffu, lrow0, 2);
    lrow1 += __shfl_xor_sync(0xffffffffu, lrow1, 1);
    lrow1 += __shfl_xor_sync(0xffffffffu, lrow1, 2);
    float inv0 = 1.f / lrow0, inv1 = 1.f / lrow1;
    #pragma unroll
    for (int jd = 0; jd < 8; jd++) {
        int col = h * 64 + jd * 8 + 2 * lc;
        float* p0 = o + (long long)(b * L_ + qrow0 + lr) * DM + col;
        p0[0] = o_acc[jd][0] * inv0;
        p0[1] = o_acc[jd][1] * inv0;
        float* p1 = o + (long long)(b * L_ + qrow0 + lr + 8) * DM + col;
        p1[0] = o_acc[jd][2] * inv1;
        p1[1] = o_acc[jd][3] * inv1;
    }
}

// ---------------- tensor-core SSD chunk-states ----------------
// states[n,p] = sum_l (B[l,n]*dec[l]) * xdt[l,p]  per (b,h,chunk).
// grid = B*HS*NC, 256 threads = 8 warps; M=128 (n), N=64 (p), K=256 (l) in 4 tiles.
__global__ __launch_bounds__(256)
void states_tc_kernel(const float* __restrict__ xbc, const float* __restrict__ xdt,
                      const float* __restrict__ Acs, float* __restrict__ states)
{
    extern __shared__ uint32_t dynst[];
    uint32_t* Ah = dynst;                    // [128][36] words
    uint32_t* Al = Ah + 128 * 36;
    uint32_t* Bh = Al + 128 * 36;            // [64][36]
    uint32_t* Bl = Bh + 64 * 36;
    float* dec_sh = (float*)(Bl + 64 * 36);  // 256
    __nv_bfloat16* Ah_e = (__nv_bfloat16*)Ah;
    __nv_bfloat16* Al_e = (__nv_bfloat16*)Al;
    __nv_bfloat16* Bh_e = (__nv_bfloat16*)Bh;
    __nv_bfloat16* Bl_e = (__nv_bfloat16*)Bl;

    int blk = blockIdx.x;
    int ck = blk & 7;
    int bh = blk >> 3;
    int h = bh & 31, b = bh >> 5;
    int tid = threadIdx.x;
    int wid = tid >> 5, lane = tid & 31;
    int lr = lane >> 2, lc = lane & 3;
    long long rowbase = (long long)(b * L_ + ck * 256);

    dec_sh[tid] = Acs[(long long)bh * L_ + ck * 256 + tid];
    __syncthreads();
    float aLast = dec_sh[255];
    float mya = dec_sh[tid];
    __syncthreads();
    dec_sh[tid] = __expf(aLast - mya);

    float acc[8][4];
    #pragma unroll
    for (int j = 0; j < 8; j++)
        #pragma unroll
        for (int r = 0; r < 4; r++) acc[j][r] = 0.f;

    for (int kt = 0; kt < 4; kt++) {
        int l0 = kt * 64;
        // A[n][c] = B[l0+c, n] * dec[l0+c]  (n fast -> coalesced)
        #pragma unroll
        for (int i = 0; i < 32; i++) {
            int idx = tid + i * 256;
            int n = idx & 127;
            int c = idx >> 7;
            float v = xbc[(rowbase + l0 + c) * CONVD + DI + n] * dec_sh[l0 + c];
            __nv_bfloat16 hi, lo; split_bf16(v, hi, lo);
            Ah_e[n * 72 + c] = hi;
            Al_e[n * 72 + c] = lo;
        }
        // B[p][c] = xdt[l0+c, h*64+p]  (p fast -> coalesced)
        #pragma unroll
        for (int i = 0; i < 16; i++) {
            int idx = tid + i * 256;
            int p = idx & 63;
            int c = idx >> 6;
            float v = xdt[(rowbase + l0 + c) * DI + h * 64 + p];
            __nv_bfloat16 hi, lo; split_bf16(v, hi, lo);
            Bh_e[p * 72 + c] = hi;
            Bl_e[p * 72 + c] = lo;
        }
        __syncthreads();
        #pragma unroll
        for (int kk2 = 0; kk2 < 32; kk2 += 8) {
            int r = wid * 16 + lr;
            uint32_t ah[4], al[4];
            ah[0] = Ah[r * 36 + kk2 + lc];
            ah[1] = Ah[(r + 8) * 36 + kk2 + lc];
            ah[2] = Ah[r * 36 + kk2 + lc + 4];
            ah[3] = Ah[(r + 8) * 36 + kk2 + lc + 4];
            al[0] = Al[r * 36 + kk2 + lc];
            al[1] = Al[(r + 8) * 36 + kk2 + lc];
            al[2] = Al[r * 36 + kk2 + lc + 4];
            al[3] = Al[(r + 8) * 36 + kk2 + lc + 4];
            #pragma unroll
            for (int jn = 0; jn < 8; jn++) {
                int n = jn * 8 + lr;
                uint32_t bhf[2], blf[2];
                bhf[0] = Bh[n * 36 + kk2 + lc];
                bhf[1] = Bh[n * 36 + kk2 + lc + 4];
                blf[0] = Bl[n * 36 + kk2 + lc];
                blf[1] = Bl[n * 36 + kk2 + lc + 4];
                mma_bf16(acc[jn], ah, blf);
                mma_bf16(acc[jn], al, bhf);
                mma_bf16(acc[jn], ah, bhf);
            }
        }
        __syncthreads();
    }

    float* base = states + (long long)(bh * NC + ck) * 8192;
    int n0 = wid * 16 + lr;
    #pragma unroll
    for (int jn = 0; jn < 8; jn++) {
        int p = jn * 8 + 2 * lc;
        float* p0 = base + n0 * 64 + p;
        p0[0] = acc[jn][0];
        p0[1] = acc[jn][1];
        float* p1 = base + (n0 + 8) * 64 + p;
        p1[0] = acc[jn][2];
        p1[1] = acc[jn][3];
    }
}

// ---------------- tensor-core SSD output ----------------
// Y[l,p] = sum_s G[l,s]*xdt[s,p] + sum_n (C[l,n]*e^{aL}) * Sprev[n,p] + D*xs
// G[l,s] = CB[s,l]*exp(acs_l - acs_s) masked (s<=l).
// grid = B*HS*NC*2 (l-halves of 128), 256 threads = 8 warps.
__global__ __launch_bounds__(256)
void y_tc_kernel(const float* __restrict__ xbc, const float* __restrict__ xdt,
                 const float* __restrict__ Acs, const float* __restrict__ CB,
                 const float* __restrict__ Sprev, const float* __restrict__ Dv,
                 float* __restrict__ Y)
{
    extern __shared__ uint32_t dyny[];
    uint32_t* Ah = dyny;                     // [128][36]
    uint32_t* Al = Ah + 128 * 36;
    uint32_t* Bh = Al + 128 * 36;            // [64][36]
    uint32_t* Bl = Bh + 64 * 36;
    float* acs_sh = (float*)(Bl + 64 * 36);  // 256
    float* eA_sh  = acs_sh + 256;            // 128
    __nv_bfloat16* Ah_e = (__nv_bfloat16*)Ah;
    __nv_bfloat16* Al_e = (__nv_bfloat16*)Al;
    __nv_bfloat16* Bh_e = (__nv_bfloat16*)Bh;
    __nv_bfloat16* Bl_e = (__nv_bfloat16*)Bl;

    int blk = blockIdx.x;
    int lh = blk & 1;
    int ck = (blk >> 1) & 7;
    int bh = blk >> 4;
    int h = bh & 31, b = bh >> 5;
    int tid = threadIdx.x;
    int wid = tid >> 5, lane = tid & 31;
    int lr = lane >> 2, lc = lane & 3;
    long long rowbase = (long long)(b * L_ + ck * 256);

    acs_sh[tid] = Acs[(long long)bh * L_ + ck * 256 + tid];
    __syncthreads();
    if (tid < 128) eA_sh[tid] = __expf(acs_sh[lh * 128 + tid]);
    // (eA used only after later __syncthreads barriers)

    float acc[8][4];
    #pragma unroll
    for (int j = 0; j < 8; j++)
        #pragma unroll
        for (int r = 0; r < 4; r++) acc[j][r] = 0.f;

    const float* cbp = CB + (long long)(b * NC + ck) * (CH * CH);
    int ndiag = (lh == 0) ? 2 : 4;

    for (int kt = 0; kt < ndiag + 2; kt++) {
        if (kt < ndiag) {
            int s0 = kt * 64;
            // A[l][s] = masked CB*exp   (l fast -> coalesced CB read)
            #pragma unroll
            for (int i = 0; i < 32; i++) {
                int idx = tid + i * 256;
                int l = idx & 127;
                int s = idx >> 7;
                int gl = lh * 128 + l;
                int gs = s0 + s;
                float v = 0.f;
                if (gs <= gl) v = cbp[gs * 256 + gl] * __expf(acs_sh[gl] - acs_sh[gs]);
                __nv_bfloat16 hi, lo; split_bf16(v, hi, lo);
                Ah_e[l * 72 + s] = hi;
                Al_e[l * 72 + s] = lo;
            }
            // B[p][s] = xdt[s0+s, h*64+p]   (p fast -> coalesced)
            #pragma unroll
            for (int i = 0; i < 16; i++) {
                int idx = tid + i * 256;
                int p = idx & 63;
                int s = idx >> 6;
                float v = xdt[(rowbase + s0 + s) * DI + h * 64 + p];
                __nv_bfloat16 hi, lo; split_bf16(v, hi, lo);
                Bh_e[p * 72 + s] = hi;
                Bl_e[p * 72 + s] = lo;
            }
        } else {
            int n0 = (kt - ndiag) * 64;
            // A[l][c] = C[l, n0+c]*eA[l]    (c fast -> coalesced xbc read)
            #pragma unroll
            for (int i = 0; i < 32; i++) {
                int idx = tid + i * 256;
                int c = idx & 63;
                int l = idx >> 6;
                float v = xbc[(rowbase + lh * 128 + l) * CONVD + DI + NST + n0 + c] * eA_sh[l];
                __nv_bfloat16 hi, lo; split_bf16(v, hi, lo);
                Ah_e[l * 72 + c] = hi;
                Al_e[l * 72 + c] = lo;
            }
            // B[p][c] = Sprev[n0+c, p]      (p fast -> coalesced)
            #pragma unroll
            for (int i = 0; i < 16; i++) {
                int idx = tid + i * 256;
                int p = idx & 63;
                int c = idx >> 6;
                float v = Sprev[(long long)(bh * NC + ck) * 8192 + (n0 + c) * 64 + p];
                __nv_bfloat16 hi, lo; split_bf16(v, hi, lo);
                Bh_e[p * 72 + c] = hi;
                Bl_e[p * 72 + c] = lo;
            }
        }
        __syncthreads();
        #pragma unroll
        for (int kk2 = 0; kk2 < 32; kk2 += 8) {
            int r = wid * 16 + lr;
            uint32_t ah[4], al[4];
            ah[0] = Ah[r * 36 + kk2 + lc];
            ah[1] = Ah[(r + 8) * 36 + kk2 + lc];
            ah[2] = Ah[r * 36 + kk2 + lc + 4];
            ah[3] = Ah[(r + 8) * 36 + kk2 + lc + 4];
            al[0] = Al[r * 36 + kk2 + lc];
            al[1] = Al[(r + 8) * 36 + kk2 + lc];
            al[2] = Al[r * 36 + kk2 + lc + 4];
            al[3] = Al[(r + 8) * 36 + kk2 + lc + 4];
            #pragma unroll
            for (int jn = 0; jn < 8; jn++) {
                int n = jn * 8 + lr;
                uint32_t bhf[2], blf[2];
                bhf[0] = Bh[n * 36 + kk2 + lc];
                bhf[1] = Bh[n * 36 + kk2 + lc + 4];
                blf[0] = Bl[n * 36 + kk2 + lc];
                blf[1] = Bl[n * 36 + kk2 + lc + 4];
                mma_bf16(acc[jn], ah, blf);
                mma_bf16(acc[jn], al, bhf);
                mma_bf16(acc[jn], ah, bhf);
            }
        }
        __syncthreads();
    }

    float Dh = Dv[h];
    int r0 = wid * 16 + lr;
    #pragma unroll
    for (int jn = 0; jn < 8; jn++) {
        int col = jn * 8 + 2 * lc;
        long long grow0 = rowbase + lh * 128 + r0;
        const float* xs0 = xbc + grow0 * CONVD + h * 64 + col;
        float* yp0 = Y + grow0 * DI + h * 64 + col;
        yp0[0] = acc[jn][0] + Dh * xs0[0];
        yp0[1] = acc[jn][1] + Dh * xs0[1];
        long long grow1 = grow0 + 8;
        const float* xs1 = xbc + grow1 * CONVD + h * 64 + col;
        float* yp1 = Y + grow1 * DI + h * 64 + col;
        yp1[0] = acc[jn][2] + Dh * xs1[0];
        yp1[1] = acc[jn][3] + Dh * xs1[1];
    }
}

// ---------------- rmsnorm ----------------
__global__ void rmsnorm_kernel(const float* __restrict__ a, const float* __restrict__ b,
                               float alpha, const float* __restrict__ w,
                               float* __restrict__ out, int D)
{
    long long row = blockIdx.x;
    const float* ap = a + row * D;
    const float* bp = b ? (b + row * D) : nullptr;
    int per = D >> 8;
    float v[8];
    float ss = 0.f;
    for (int j = 0; j < per; j++) {
        int i = threadIdx.x + j * 256;
        float x = ap[i] + (bp ? alpha * bp[i] : 0.f);
        v[j] = x;
        ss += x * x;
    }
    __shared__ float red[256];
    red[threadIdx.x] = ss;
    __syncthreads();
    for (int off = 128; off; off >>= 1) {
        if (threadIdx.x < off) red[threadIdx.x] += red[threadIdx.x + off];
        __syncthreads();
    }
    float scale = rsqrtf(red[0] / D + EPSN);
    float* op = out + row * D;
    for (int j = 0; j < per; j++) {
        int i = threadIdx.x + j * 256;
        op[i] = v[j] * scale * w[i];
    }
}

// ---------------- gated rmsnorm ----------------
__global__ void gated_rmsnorm_kernel(const float* __restrict__ y, const float* __restrict__ z,
                                     int ldz, const float* __restrict__ w,
                                     float* __restrict__ out)
{
    long long row = blockIdx.x;
    const float* yp = y + row * DI;
    const float* zp = z + row * (long long)ldz;
    float v[8];
    float ss = 0.f;
    #pragma unroll
    for (int j = 0; j < 8; j++) {
        int i = threadIdx.x + j * 256;
        float x = yp[i] * silu_f(zp[i]);
        v[j] = x;
        ss += x * x;
    }
    __shared__ float red[256];
    red[threadIdx.x] = ss;
    __syncthreads();
    for (int off = 128; off; off >>= 1) {
        if (threadIdx.x < off) red[threadIdx.x] += red[threadIdx.x + off];
        __syncthreads();
    }
    float scale = rsqrtf(red[0] / DI + EPSN);
    float* op = out + row * DI;
    #pragma unroll
    for (int j = 0; j < 8; j++) {
        int i = threadIdx.x + j * 256;
        op[i] = v[j] * scale * w[i];
    }
}

// ---------------- depthwise causal conv (k=4) + bias + silu ----------------
__global__ void conv_kernel(const float* __restrict__ zx, const float* __restrict__ cw,
                            const float* __restrict__ cb, float* __restrict__ xbc)
{
    int idx = blockIdx.x * 256 + threadIdx.x;
    if (idx >= B_ * L_ * CONVD) return;
    int c = idx % CONVD;
    int t = (idx / CONVD) % L_;
    int b = idx / (CONVD * L_);
    float s = cb[c];
    #pragma unroll
    for (int k = 0; k < 4; k++) {
        int tt = t - 3 + k;
        if (tt >= 0)
            s += zx[((long long)(b * L_ + tt) * DINP) + DI + c] * cw[c * 4 + k];
    }
    xbc[idx] = silu_f(s);
}

// ---------------- dt (softplus) and xdt = xs*dt ----------------
__global__ void dtxdt_kernel(const float* __restrict__ zx, const float* __restrict__ xbc,
                             const float* __restrict__ dt_bias,
                             float* __restrict__ dtb, float* __restrict__ xdt)
{
    int idx = blockIdx.x * 256 + threadIdx.x;
    if (idx >= ROWS * DI) return;
    int p = idx & 63;
    int h = (idx >> 6) & 31;
    long long row = idx >> 11;
    float raw = zx[row * DINP + DI + CONVD + h] + dt_bias[h];
    float d = softplus_f(raw);
    xdt[idx] = xbc[row * CONVD + h * 64 + p] * d;
    if (p == 0) dtb[row * HS + h] = d;
}

// ---------------- per-chunk inclusive cumsum ----------------
__global__ void cumsum_kernel(const float* __restrict__ dtb, const float* __restrict__ A_log,
                              float* __restrict__ Acs)
{
    __shared__ float s[256];
    int blk = blockIdx.x;
    int ck = blk & 7;
    int bh = blk >> 3;
    int h = bh & 31;
    int b = bh >> 5;
    int l = threadIdx.x;
    int gl = ck * 256 + l;
    float a = -__expf(A_log[h]) * dtb[((long long)(b * L_ + gl)) * HS + h];
    s[l] = a;
    __syncthreads();
    for (int off = 1; off < 256; off <<= 1) {
        float t = (l >= off) ? s[l - off] : 0.f;
        __syncthreads();
        s[l] += t;
        __syncthreads();
    }
    Acs[(long long)bh * L_ + gl] = s[l];
}

// ---------------- inter-chunk scan ----------------
__global__ void scan_kernel(const float* __restrict__ states, const float* __restrict__ Acs,
                            float* __restrict__ Sprev)
{
    int bh = blockIdx.x;
    int tid = threadIdx.x;
    float S[32];
    #pragma unroll
    for (int j = 0; j < 32; j++) S[j] = 0.f;
    for (int c = 0; c < NC; c++) {
        float dc = __expf(Acs[(long long)bh * L_ + c * 256 + 255]);
        const float* sp = states + (long long)(bh * NC + c) * 8192;
        float* pp = Sprev + (long long)(bh * NC + c) * 8192;
        #pragma unroll
        for (int j = 0; j < 32; j++) {
            int idx = tid + j * 256;
            pp[idx] = S[j];
            S[j] = S[j] * dc + sp[idx];
        }
    }
}

// ---------------- swiglu ----------------
__global__ void swiglu_kernel(const float* __restrict__ y, float* __restrict__ ff)
{
    int idx = blockIdx.x * 256 + threadIdx.x;
    if (idx >= ROWS * DFF) return;
    long long row = idx / DFF;
    int f = idx % DFF;
    const float* yp = y + row * (2 * DFF);
    ff[idx] = yp[f] * silu_f(yp[f + DFF]);
}

// ---------------- host launcher ----------------
#define SSD_SMEM 57344

extern "C" void kernel_launch(void* const* d_in, const int* in_sizes, int n_in,
                              void* d_out, int out_size)
{
    const float* x_in       = (const float*)d_in[0];
    const float* attn_norm  = (const float*)d_in[1];
    const float* Wqkv       = (const float*)d_in[2];
    const float* Wqkv_b     = (const float*)d_in[3];
    const float* attn_out_w = (const float*)d_in[4];
    const float* attn_out_b = (const float*)d_in[5];
    const float* normf_w    = (const float*)d_in[6];
    const float* m_in_w     = (const float*)d_in[7];
    const float* m_conv_w   = (const float*)d_in[8];
    const float* m_conv_b   = (const float*)d_in[9];
    const float* m_dt_bias  = (const float*)d_in[10];
    const float* m_A_log    = (const float*)d_in[11];
    const float* m_D        = (const float*)d_in[12];
    const float* m_norm_w   = (const float*)d_in[13];
    const float* m_out_w    = (const float*)d_in[14];
    const float* fc1_w      = (const float*)d_in[15];
    const float* fc2_w      = (const float*)d_in[16];
    const float* final_norm = (const float*)d_in[17];
    float* out = (float*)d_out;

    float* scr = nullptr;
    cudaGetSymbolAddress((void**)&scr, g_scratch);

    cudaFuncSetAttribute(states_tc_kernel, cudaFuncAttributeMaxDynamicSharedMemorySize, SSD_SMEM);
    cudaFuncSetAttribute(y_tc_kernel, cudaFuncAttributeMaxDynamicSharedMemorySize, SSD_SMEM);

    float* bBIG = scr + OFF_BIG;
    float* bH   = scr + OFF_H;
    float* bO   = scr + OFF_O;
    float* bX   = scr + OFF_X;
    float* bXBC = scr + OFF_XBC;
    float* bDT  = scr + OFF_DT;
    float* bXDT = scr + OFF_XDT;
    float* bACS = scr + OFF_ACS;
    float* bCB  = scr + OFF_CB;
    float* bSTA = scr + OFF_STA;
    float* bSPR = scr + OFF_SPR;
    float* bY   = scr + OFF_Y;
    float* bFF  = scr + OFF_FF;

    // ---- attention block ----
    rmsnorm_kernel<<<ROWS, 256>>>(x_in, nullptr, 0.f, attn_norm, bH, DM);
    gemm_tc<<<dim3(3072/128, ROWS/128, 1), 256>>>(bH, Wqkv, Wqkv_b, bBIG,
        ROWS, 3072, DM, DM, DM, 3072, 0, 0, 0);
    attn_tc_kernel<<<dim3(L_/128, B_*NH), 256>>>(bBIG, bO);
    gemm_tc<<<dim3(DM/128, ROWS/128, 1), 256>>>(bO, attn_out_w, attn_out_b, bH,
        ROWS, DM, DM, DM, DM, DM, 0, 0, 0);
    rmsnorm_kernel<<<ROWS, 256>>>(bH, x_in, 1.f, normf_w, bX, DM);

    // ---- mamba layers ----
    for (int i = 0; i < 4; i++) {
        const float* in_w   = m_in_w   + (long long)i * DINP * DM;
        const float* conv_w = m_conv_w + (long long)i * CONVD * 4;
        const float* conv_b = m_conv_b + (long long)i * CONVD;
        const float* dtbias = m_dt_bias+ (long long)i * HS;
        const float* Alog   = m_A_log  + (long long)i * HS;
        const float* Dv     = m_D      + (long long)i * HS;
        const float* nw     = m_norm_w + (long long)i * DI;
        const float* ow     = m_out_w  + (long long)i * DM * DI;

        gemm_tc<<<dim3((DINP+127)/128, ROWS/128, 1), 256>>>(bX, in_w, nullptr, bBIG,
            ROWS, DINP, DM, DM, DM, DINP, 0, 0, 0);
        conv_kernel<<<(ROWS*CONVD)/256, 256>>>(bBIG, conv_w, conv_b, bXBC);
        dtxdt_kernel<<<(ROWS*DI)/256, 256>>>(bBIG, bXBC, dtbias, bDT, bXDT);
        cumsum_kernel<<<B_*HS*NC, 256>>>(bDT, Alog, bACS);
        gemm_tc<<<dim3(2, 2, B_*NC), 256>>>(
            bXBC + DI, bXBC + DI + NST, nullptr, bCB,
            CH, CH, NST, CONVD, CONVD, CH,
            (long long)CH * CONVD, (long long)CH * CONVD, (long long)CH * CH);
        states_tc_kernel<<<B_*HS*NC, 256, SSD_SMEM>>>(bXBC, bXDT, bACS, bSTA);
        scan_kernel<<<B_*HS, 256>>>(bSTA, bACS, bSPR);
        y_tc_kernel<<<B_*HS*NC*2, 256, SSD_SMEM>>>(bXBC, bXDT, bACS, bCB, bSPR, Dv, bY);
        gated_rmsnorm_kernel<<<ROWS, 256>>>(bY, bBIG, DINP, nw, bY);
        gemm_tc<<<dim3(DM/128, ROWS/128, 1), 256>>>(bY, ow, nullptr, bX,
            ROWS, DM, DI, DI, DI, DM, 0, 0, 0);
    }

    // ---- MLP + final norm ----
    gemm_tc<<<dim3((2*DFF)/128, ROWS/128, 1), 256>>>(bX, fc1_w, nullptr, bBIG,
        ROWS, 2*DFF, DM, DM, DM, 2*DFF, 0, 0, 0);
    swiglu_kernel<<<(ROWS*DFF)/256, 256>>>(bBIG, bFF);
    gemm_tc<<<dim3(DM/128, ROWS/128, 1), 256>>>(bFF, fc2_w, nullptr, bH,
        ROWS, DM, DFF, DFF, DFF, DM, 0, 0, 0);
    rmsnorm_kernel<<<ROWS, 256>>>(bH, bX, ALPHA, final_norm, out, DM);
}